// round 5
// baseline (speedup 1.0000x reference)
#include <cuda_runtime.h>
#include <math.h>

#define B_ROWS 4096
#define KTOK   64
#define DM     256
#define DDYN   512
#define NH     4
#define SCALE  0.125f
#define LN_EPS 1e-5f
#define WT_STRIDE 260   // padded smem stride for weight tiles
#define AST       260   // padded smem stride for activation tiles

// ---- scratch (allocation-free rule: __device__ globals) ----
__device__ float g_h0 [B_ROWS * DM];        // 4 MB
__device__ float g_u  [B_ROWS * DM * NH];   // 16 MB : u[b][j][h]
__device__ float g_qbk[B_ROWS * NH];        // 64 KB

// ============================================================
// Shared-memory tiled GEMM: C[rows,256] = Asm[rows,kdim] @ Wg[kdim,256]
// Thread tile 4 tokens x 8 cols. rows = 4 * (blockDim/32).
// Weight rows streamed through 16x256 smem tile (padded stride).
// ============================================================
template<int NTHREADS>
__device__ __forceinline__ void gemm_acc(
    const float* __restrict__ Asm, int astride, int kdim,
    const float* __restrict__ Wg, float* __restrict__ Wt,
    float acc[4][8], int tid)
{
#pragma unroll
    for (int t = 0; t < 4; t++)
#pragma unroll
        for (int j = 0; j < 8; j++) acc[t][j] = 0.f;

    const int tc   = tid & 31;
    const int tok0 = (tid >> 5) * 4;
    const int col0 = tc * 8;
    const int nkt  = kdim >> 4;

    for (int kt = 0; kt < nkt; ++kt) {
        // stage 16 weight rows (16x256 floats) into smem, coalesced
        const float4* src = reinterpret_cast<const float4*>(Wg + kt * 16 * DM);
#pragma unroll
        for (int f = tid; f < 1024; f += NTHREADS) {
            int row = f >> 6, c4 = f & 63;
            float4 v = src[f];
            *reinterpret_cast<float4*>(Wt + row * WT_STRIDE + c4 * 4) = v;
        }
        __syncthreads();
#pragma unroll
        for (int kk4 = 0; kk4 < 4; ++kk4) {
            const int kbase = kt * 16 + kk4 * 4;
            float a_[4][4];
#pragma unroll
            for (int t = 0; t < 4; t++) {
                float4 v = *reinterpret_cast<const float4*>(Asm + (tok0 + t) * astride + kbase);
                a_[t][0] = v.x; a_[t][1] = v.y; a_[t][2] = v.z; a_[t][3] = v.w;
            }
#pragma unroll
            for (int r = 0; r < 4; r++) {
                const float4 w0 = *reinterpret_cast<const float4*>(Wt + (kk4 * 4 + r) * WT_STRIDE + col0);
                const float4 w1 = *reinterpret_cast<const float4*>(Wt + (kk4 * 4 + r) * WT_STRIDE + col0 + 4);
                float w[8] = {w0.x, w0.y, w0.z, w0.w, w1.x, w1.y, w1.z, w1.w};
#pragma unroll
                for (int t = 0; t < 4; t++) {
                    const float a = a_[t][r];
#pragma unroll
                    for (int j = 0; j < 8; j++)
                        acc[t][j] = fmaf(a, w[j], acc[t][j]);
                }
            }
        }
        __syncthreads();
    }
}

// epilogue: add bias, LayerNorm per token row, write to smem (strided)
__device__ __forceinline__ void epi_ln(
    float acc[4][8], const float* __restrict__ bias,
    const float* __restrict__ g, const float* __restrict__ bn,
    float* __restrict__ out, int ostride, int tid)
{
    const int tc = tid & 31, tok0 = (tid >> 5) * 4, col0 = tc * 8;
#pragma unroll
    for (int t = 0; t < 4; t++) {
        float s = 0.f, s2 = 0.f;
#pragma unroll
        for (int j = 0; j < 8; j++) {
            float v = acc[t][j] + bias[col0 + j];
            acc[t][j] = v; s += v; s2 += v * v;
        }
#pragma unroll
        for (int off = 16; off; off >>= 1) {
            s  += __shfl_xor_sync(0xffffffffu, s,  off);
            s2 += __shfl_xor_sync(0xffffffffu, s2, off);
        }
        float mean = s * (1.f / 256.f);
        float var  = s2 * (1.f / 256.f) - mean * mean;
        float rstd = rsqrtf(var + LN_EPS);
#pragma unroll
        for (int j = 0; j < 8; j++) {
            float v = (acc[t][j] - mean) * rstd;
            out[(tok0 + t) * ostride + col0 + j] = v * g[col0 + j] + bn[col0 + j];
        }
    }
}

// ============================================================
// Kernel 1: per 32 batch rows.
// h0 = h_dyn@W_dyn + b_dyn  (store)  ->  LN  ->  q = h@Wq + bq
// u[b,j,h] = sum_d Wk[j,64h+d]*q[64h+d] ;  qbk[b,h] = q_h . bk_h
// ============================================================
__global__ void __launch_bounds__(256, 1) k1(
    const float* __restrict__ h_dyn, const float* __restrict__ W_dyn,
    const float* __restrict__ b_dyn, const float* __restrict__ g_ndyn,
    const float* __restrict__ b_ndyn, const float* __restrict__ Wq,
    const float* __restrict__ bq, const float* __restrict__ Wk,
    const float* __restrict__ bk)
{
    extern __shared__ float sm[];
    float* sm_hd  = sm;                      // 32*512
    float* sm_h   = sm_hd + 32 * 512;        // 32*256
    float* sm_q   = sm_h  + 32 * 256;        // 32*256
    float* sm_wt  = sm_q  + 32 * 256;        // 16*260
    float* p_bdyn = sm_wt + 16 * WT_STRIDE;  // 5 x 256 params
    float* p_gn   = p_bdyn + 256;
    float* p_bn   = p_gn + 256;
    float* p_bq   = p_bn + 256;
    float* p_bk   = p_bq + 256;

    const int tid  = threadIdx.x;
    const int row0 = blockIdx.x * 32;

    {
        const float4* src = reinterpret_cast<const float4*>(h_dyn + (size_t)row0 * DDYN);
        for (int f = tid; f < 32 * 512 / 4; f += 256)
            reinterpret_cast<float4*>(sm_hd)[f] = src[f];
    }
    if (tid < 64) {
        reinterpret_cast<float4*>(p_bdyn)[tid] = reinterpret_cast<const float4*>(b_dyn)[tid];
        reinterpret_cast<float4*>(p_gn)[tid]   = reinterpret_cast<const float4*>(g_ndyn)[tid];
        reinterpret_cast<float4*>(p_bn)[tid]   = reinterpret_cast<const float4*>(b_ndyn)[tid];
        reinterpret_cast<float4*>(p_bq)[tid]   = reinterpret_cast<const float4*>(bq)[tid];
        reinterpret_cast<float4*>(p_bk)[tid]   = reinterpret_cast<const float4*>(bk)[tid];
    }
    __syncthreads();

    float acc[4][8];
    // ---- h0 = h_dyn @ W_dyn ----
    gemm_acc<256>(sm_hd, 512, 512, W_dyn, sm_wt, acc, tid);
    {
        const int tc = tid & 31, tok0 = (tid >> 5) * 4, col0 = tc * 8;
#pragma unroll
        for (int t = 0; t < 4; t++) {
            float s = 0.f, s2 = 0.f;
#pragma unroll
            for (int j = 0; j < 8; j++) {
                float v = acc[t][j] + p_bdyn[col0 + j];
                acc[t][j] = v; s += v; s2 += v * v;
            }
            float* h0p = g_h0 + (size_t)(row0 + tok0 + t) * DM + col0;
            reinterpret_cast<float4*>(h0p)[0] = make_float4(acc[t][0], acc[t][1], acc[t][2], acc[t][3]);
            reinterpret_cast<float4*>(h0p)[1] = make_float4(acc[t][4], acc[t][5], acc[t][6], acc[t][7]);
#pragma unroll
            for (int off = 16; off; off >>= 1) {
                s  += __shfl_xor_sync(0xffffffffu, s,  off);
                s2 += __shfl_xor_sync(0xffffffffu, s2, off);
            }
            float mean = s * (1.f / 256.f);
            float var  = s2 * (1.f / 256.f) - mean * mean;
            float rstd = rsqrtf(var + LN_EPS);
#pragma unroll
            for (int j = 0; j < 8; j++)
                sm_h[(tok0 + t) * DM + col0 + j] =
                    (acc[t][j] - mean) * rstd * p_gn[col0 + j] + p_bn[col0 + j];
        }
    }
    __syncthreads();

    // ---- q = h_ln @ Wq + bq ----
    gemm_acc<256>(sm_h, 256, 256, Wq, sm_wt, acc, tid);
    {
        const int tc = tid & 31, tok0 = (tid >> 5) * 4, col0 = tc * 8;
#pragma unroll
        for (int t = 0; t < 4; t++)
#pragma unroll
            for (int j = 0; j < 8; j++)
                sm_q[(tok0 + t) * DM + col0 + j] = acc[t][j] + p_bq[col0 + j];
    }
    __syncthreads();

    // ---- u[b,j,h] via staged Wk tiles ----
    for (int jt = 0; jt < 16; jt++) {
        const float4* src = reinterpret_cast<const float4*>(Wk + jt * 16 * DM);
        for (int f = tid; f < 1024; f += 256) {
            int r = f >> 6, c4 = f & 63;
            *reinterpret_cast<float4*>(sm_wt + r * WT_STRIDE + c4 * 4) = src[f];
        }
        __syncthreads();
        const int jl = tid & 15;
#pragma unroll
        for (int rr = 0; rr < 2; rr++) {
            const int r = (tid >> 4) + rr * 16;
            float ua[4];
#pragma unroll
            for (int h = 0; h < 4; h++) {
                float a = 0.f;
#pragma unroll
                for (int d4 = 0; d4 < 16; d4++) {
                    float4 qv = *reinterpret_cast<const float4*>(sm_q + r * DM + h * 64 + d4 * 4);
                    float4 wv = *reinterpret_cast<const float4*>(sm_wt + jl * WT_STRIDE + h * 64 + d4 * 4);
                    a += qv.x * wv.x + qv.y * wv.y + qv.z * wv.z + qv.w * wv.w;
                }
                ua[h] = a;
            }
            *reinterpret_cast<float4*>(g_u + (size_t)(row0 + r) * (DM * NH) + (jt * 16 + jl) * 4) =
                make_float4(ua[0], ua[1], ua[2], ua[3]);
        }
        __syncthreads();
    }

    // ---- qbk[b,h] ----
    if (tid < 128) {
        const int r = tid >> 2, h = tid & 3;
        float a = 0.f;
#pragma unroll
        for (int d = 0; d < 64; d++)
            a += sm_q[r * DM + h * 64 + d] * p_bk[h * 64 + d];
        g_qbk[(size_t)(row0 + r) * 4 + h] = a;
    }
}

// ============================================================
// Kernel 2: one block per batch row b. Full fused token path.
// ============================================================
__global__ void __launch_bounds__(512, 1) k2(
    const float* __restrict__ x_stat,
    const float* __restrict__ W_stat, const float* __restrict__ b_stat,
    const float* __restrict__ g_nstat, const float* __restrict__ b_nstat,
    const float* __restrict__ Wv, const float* __restrict__ bv,
    const float* __restrict__ g_mlp, const float* __restrict__ b_mlp,
    const float* __restrict__ W1, const float* __restrict__ b1,
    const float* __restrict__ W2, const float* __restrict__ b2,
    const float* __restrict__ Wo, const float* __restrict__ bo,
    const float* __restrict__ res_scale_p,
    float* __restrict__ out)
{
    extern __shared__ float sm[];
    float* A    = sm;                      // 64*260
    float* Bb   = A   + 64 * AST;          // 64*260
    float* xs   = Bb  + 64 * AST;          // 64*64
    float* Wt   = xs  + 64 * 64;           // 16*260
    float* us   = Wt  + 16 * WT_STRIDE;    // 1024 : u[j*4+h]
    float* pb   = us  + 1024;              // 10*256 params (see order below)
    float* wsm  = pb  + 10 * 256;          // 256 : w[h*64+k]
    float* zsm  = wsm + 256;               // 256
    float* ssum = zsm + 256;               // 8
    float* qbks = ssum + 8;                // 8

    const int tid = threadIdx.x;
    const int b   = blockIdx.x;

    // ---- cooperative loads ----
    {
        const float4* src = reinterpret_cast<const float4*>(x_stat + (size_t)b * 64 * 64);
        for (int f = tid; f < 1024; f += 512) reinterpret_cast<float4*>(xs)[f] = src[f];
        if (tid < 256)
            reinterpret_cast<float4*>(us)[tid] =
                reinterpret_cast<const float4*>(g_u + (size_t)b * 1024)[tid];
        if (tid < 64) {
            reinterpret_cast<float4*>(pb + 0 * 256)[tid] = reinterpret_cast<const float4*>(b_stat)[tid];
            reinterpret_cast<float4*>(pb + 1 * 256)[tid] = reinterpret_cast<const float4*>(g_nstat)[tid];
            reinterpret_cast<float4*>(pb + 2 * 256)[tid] = reinterpret_cast<const float4*>(b_nstat)[tid];
            reinterpret_cast<float4*>(pb + 3 * 256)[tid] = reinterpret_cast<const float4*>(bv)[tid];
            reinterpret_cast<float4*>(pb + 4 * 256)[tid] = reinterpret_cast<const float4*>(g_mlp)[tid];
            reinterpret_cast<float4*>(pb + 5 * 256)[tid] = reinterpret_cast<const float4*>(b_mlp)[tid];
            reinterpret_cast<float4*>(pb + 6 * 256)[tid] = reinterpret_cast<const float4*>(b1)[tid];
            reinterpret_cast<float4*>(pb + 7 * 256)[tid] = reinterpret_cast<const float4*>(b2)[tid];
            reinterpret_cast<float4*>(pb + 8 * 256)[tid] = reinterpret_cast<const float4*>(bo)[tid];
            reinterpret_cast<float4*>(pb + 9 * 256)[tid] =
                reinterpret_cast<const float4*>(g_h0 + (size_t)b * 256)[tid];
        }
        if (tid < 4) qbks[tid] = g_qbk[(size_t)b * 4 + tid];
    }
    __syncthreads();

    float acc[4][8];

    // ---- S1: s = x_stat @ W_stat + b_stat ; LN -> A ----
    gemm_acc<512>(xs, 64, 64, W_stat, Wt, acc, tid);
    epi_ln(acc, pb + 0 * 256, pb + 1 * 256, pb + 2 * 256, A, AST, tid);
    __syncthreads();

    // ---- logits / sigmoid / normalize / w_mean ----
    if (tid < 256) {
        const int k = tid >> 2, h = tid & 3;
        float a = qbks[h];
        const float* ar = A + k * AST;
#pragma unroll 4
        for (int j = 0; j < 256; j++) a += ar[j] * us[j * 4 + h];
        float lg = a * SCALE;
        wsm[h * 64 + k] = 1.f / (1.f + expf(-lg));
    }
    __syncthreads();
    if (tid < 4) {
        float s = 0.f;
        for (int k = 0; k < 64; k++) s += wsm[tid * 64 + k];
        ssum[tid] = s + 1e-6f;
    }
    __syncthreads();
    if (tid < 256) wsm[tid] = wsm[tid] / ssum[tid >> 6];
    __syncthreads();
    if (tid < 64)
        out[(size_t)B_ROWS * DM + (size_t)b * 64 + tid] =
            0.25f * (wsm[tid] + wsm[64 + tid] + wsm[128 + tid] + wsm[192 + tid]);

    // ---- S2: v = A @ Wv + bv ; LN(g_mlp) -> Bb ----
    gemm_acc<512>(A, AST, 256, Wv, Wt, acc, tid);
    epi_ln(acc, pb + 3 * 256, pb + 4 * 256, pb + 5 * 256, Bb, AST, tid);
    __syncthreads();

    // ---- S3: t = gelu(Bb @ W1 + b1) -> A ----
    gemm_acc<512>(Bb, AST, 256, W1, Wt, acc, tid);
    {
        const int tc = tid & 31, tok0 = (tid >> 5) * 4, col0 = tc * 8;
#pragma unroll
        for (int t = 0; t < 4; t++)
#pragma unroll
            for (int j = 0; j < 8; j++) {
                float x = acc[t][j] + pb[6 * 256 + col0 + j];
                A[(tok0 + t) * AST + col0 + j] = 0.5f * x * (1.f + erff(x * 0.70710678118f));
            }
    }
    __syncthreads();

    // ---- S4: vtok = A @ W2 + b2 -> Bb ----
    gemm_acc<512>(A, AST, 256, W2, Wt, acc, tid);
    {
        const int tc = tid & 31, tok0 = (tid >> 5) * 4, col0 = tc * 8;
#pragma unroll
        for (int t = 0; t < 4; t++)
#pragma unroll
            for (int j = 0; j < 8; j++)
                Bb[(tok0 + t) * AST + col0 + j] = acc[t][j] + pb[7 * 256 + col0 + j];
    }
    __syncthreads();

    // ---- z[d] = sum_k w[h(d),k] * vtok[k,d] ----
    if (tid < 256) {
        const int d = tid, h = d >> 6;
        float a = 0.f;
        const float* wr = wsm + h * 64;
#pragma unroll 8
        for (int k = 0; k < 64; k++) a += wr[k] * Bb[k * AST + d];
        zsm[d] = a;
    }
    __syncthreads();

    // ---- c = z @ Wo + bo ; out = h0 + res_scale*c ----
    if (tid < 256) {
        const int d = tid;
        float a = 0.f;
#pragma unroll 8
        for (int i = 0; i < 256; i++) a += zsm[i] * Wo[i * DM + d];
        float rs = *res_scale_p;
        out[(size_t)b * DM + d] = pb[9 * 256 + d] + rs * (a + pb[8 * 256 + d]);
    }
}

// ============================================================
extern "C" void kernel_launch(void* const* d_in, const int* in_sizes, int n_in,
                              void* d_out, int out_size)
{
    const float* h_dyn   = (const float*)d_in[0];
    const float* x_stat  = (const float*)d_in[1];
    const float* W_dyn   = (const float*)d_in[2];
    const float* b_dyn   = (const float*)d_in[3];
    const float* W_stat  = (const float*)d_in[4];
    const float* b_stat  = (const float*)d_in[5];
    const float* g_ndyn  = (const float*)d_in[6];
    const float* b_ndyn  = (const float*)d_in[7];
    const float* g_nstat = (const float*)d_in[8];
    const float* b_nstat = (const float*)d_in[9];
    const float* Wq      = (const float*)d_in[10];
    const float* bq      = (const float*)d_in[11];
    const float* Wk      = (const float*)d_in[12];
    const float* bk      = (const float*)d_in[13];
    const float* Wv      = (const float*)d_in[14];
    const float* bv      = (const float*)d_in[15];
    const float* g_mlp   = (const float*)d_in[16];
    const float* b_mlp   = (const float*)d_in[17];
    const float* W1      = (const float*)d_in[18];
    const float* b1      = (const float*)d_in[19];
    const float* W2      = (const float*)d_in[20];
    const float* b2      = (const float*)d_in[21];
    const float* Wo      = (const float*)d_in[22];
    const float* bo      = (const float*)d_in[23];
    const float* res_sc  = (const float*)d_in[24];
    float* out = (float*)d_out;

    const int SMEM1 = (32 * 512 + 32 * 256 + 32 * 256 + 16 * WT_STRIDE + 5 * 256) * 4;
    const int SMEM2 = (64 * AST * 2 + 64 * 64 + 16 * WT_STRIDE + 1024 + 10 * 256 + 256 + 256 + 16) * 4;

    cudaFuncSetAttribute(k1, cudaFuncAttributeMaxDynamicSharedMemorySize, SMEM1);
    cudaFuncSetAttribute(k2, cudaFuncAttributeMaxDynamicSharedMemorySize, SMEM2);

    k1<<<B_ROWS / 32, 256, SMEM1>>>(h_dyn, W_dyn, b_dyn, g_ndyn, b_ndyn, Wq, bq, Wk, bk);
    k2<<<B_ROWS, 512, SMEM2>>>(x_stat, W_stat, b_stat, g_nstat, b_nstat,
                               Wv, bv, g_mlp, b_mlp, W1, b1, W2, b2, Wo, bo,
                               res_sc, out);
}

// round 6
// speedup vs baseline: 1.0001x; 1.0001x over previous
#include <cuda_runtime.h>
#include <math.h>

#define B_ROWS 4096
#define KTOK   64
#define DM     256
#define DDYN   512
#define NH     4
#define SCALE  0.125f
#define LN_EPS 1e-5f
#define WT_STRIDE 260   // padded smem stride for weight tiles
#define AST       260   // padded smem stride for activation tiles

// ---- scratch (allocation-free rule: __device__ globals) ----
__device__ float g_h0 [B_ROWS * DM];        // 4 MB
__device__ float g_u  [B_ROWS * DM * NH];   // 16 MB : u[b][j][h]
__device__ float g_qbk[B_ROWS * NH];        // 64 KB

// ============================================================
// Shared-memory tiled GEMM: C[rows,256] = Asm[rows,kdim] @ Wg[kdim,256]
// Thread tile 4 tokens x 8 cols. rows = 4 * (blockDim/32).
// Weight rows streamed through 16x256 smem tile (padded stride).
// ============================================================
template<int NTHREADS>
__device__ __forceinline__ void gemm_acc(
    const float* __restrict__ Asm, int astride, int kdim,
    const float* __restrict__ Wg, float* __restrict__ Wt,
    float acc[4][8], int tid)
{
#pragma unroll
    for (int t = 0; t < 4; t++)
#pragma unroll
        for (int j = 0; j < 8; j++) acc[t][j] = 0.f;

    const int tc   = tid & 31;
    const int tok0 = (tid >> 5) * 4;
    const int col0 = tc * 8;
    const int nkt  = kdim >> 4;

    for (int kt = 0; kt < nkt; ++kt) {
        // stage 16 weight rows (16x256 floats) into smem, coalesced
        const float4* src = reinterpret_cast<const float4*>(Wg + kt * 16 * DM);
#pragma unroll
        for (int f = tid; f < 1024; f += NTHREADS) {
            int row = f >> 6, c4 = f & 63;
            float4 v = src[f];
            *reinterpret_cast<float4*>(Wt + row * WT_STRIDE + c4 * 4) = v;
        }
        __syncthreads();
#pragma unroll
        for (int kk4 = 0; kk4 < 4; ++kk4) {
            const int kbase = kt * 16 + kk4 * 4;
            float a_[4][4];
#pragma unroll
            for (int t = 0; t < 4; t++) {
                float4 v = *reinterpret_cast<const float4*>(Asm + (tok0 + t) * astride + kbase);
                a_[t][0] = v.x; a_[t][1] = v.y; a_[t][2] = v.z; a_[t][3] = v.w;
            }
#pragma unroll
            for (int r = 0; r < 4; r++) {
                const float4 w0 = *reinterpret_cast<const float4*>(Wt + (kk4 * 4 + r) * WT_STRIDE + col0);
                const float4 w1 = *reinterpret_cast<const float4*>(Wt + (kk4 * 4 + r) * WT_STRIDE + col0 + 4);
                float w[8] = {w0.x, w0.y, w0.z, w0.w, w1.x, w1.y, w1.z, w1.w};
#pragma unroll
                for (int t = 0; t < 4; t++) {
                    const float a = a_[t][r];
#pragma unroll
                    for (int j = 0; j < 8; j++)
                        acc[t][j] = fmaf(a, w[j], acc[t][j]);
                }
            }
        }
        __syncthreads();
    }
}

// epilogue: add bias, LayerNorm per token row, write to smem (strided)
__device__ __forceinline__ void epi_ln(
    float acc[4][8], const float* __restrict__ bias,
    const float* __restrict__ g, const float* __restrict__ bn,
    float* __restrict__ out, int ostride, int tid)
{
    const int tc = tid & 31, tok0 = (tid >> 5) * 4, col0 = tc * 8;
#pragma unroll
    for (int t = 0; t < 4; t++) {
        float s = 0.f, s2 = 0.f;
#pragma unroll
        for (int j = 0; j < 8; j++) {
            float v = acc[t][j] + bias[col0 + j];
            acc[t][j] = v; s += v; s2 += v * v;
        }
#pragma unroll
        for (int off = 16; off; off >>= 1) {
            s  += __shfl_xor_sync(0xffffffffu, s,  off);
            s2 += __shfl_xor_sync(0xffffffffu, s2, off);
        }
        float mean = s * (1.f / 256.f);
        float var  = s2 * (1.f / 256.f) - mean * mean;
        float rstd = rsqrtf(var + LN_EPS);
#pragma unroll
        for (int j = 0; j < 8; j++) {
            float v = (acc[t][j] - mean) * rstd;
            out[(tok0 + t) * ostride + col0 + j] = v * g[col0 + j] + bn[col0 + j];
        }
    }
}

// ============================================================
// Kernel 1: per 32 batch rows.
// h0 = h_dyn@W_dyn + b_dyn  (store)  ->  LN  ->  q = h@Wq + bq
// u[b,j,h] = sum_d Wk[j,64h+d]*q[64h+d] ;  qbk[b,h] = q_h . bk_h
// ============================================================
__global__ void __launch_bounds__(256, 1) k1(
    const float* __restrict__ h_dyn, const float* __restrict__ W_dyn,
    const float* __restrict__ b_dyn, const float* __restrict__ g_ndyn,
    const float* __restrict__ b_ndyn, const float* __restrict__ Wq,
    const float* __restrict__ bq, const float* __restrict__ Wk,
    const float* __restrict__ bk)
{
    extern __shared__ float sm[];
    float* sm_hd  = sm;                      // 32*512
    float* sm_h   = sm_hd + 32 * 512;        // 32*256
    float* sm_q   = sm_h  + 32 * 256;        // 32*256
    float* sm_wt  = sm_q  + 32 * 256;        // 16*260
    float* p_bdyn = sm_wt + 16 * WT_STRIDE;  // 5 x 256 params
    float* p_gn   = p_bdyn + 256;
    float* p_bn   = p_gn + 256;
    float* p_bq   = p_bn + 256;
    float* p_bk   = p_bq + 256;

    const int tid  = threadIdx.x;
    const int row0 = blockIdx.x * 32;

    {
        const float4* src = reinterpret_cast<const float4*>(h_dyn + (size_t)row0 * DDYN);
        for (int f = tid; f < 32 * 512 / 4; f += 256)
            reinterpret_cast<float4*>(sm_hd)[f] = src[f];
    }
    if (tid < 64) {
        reinterpret_cast<float4*>(p_bdyn)[tid] = reinterpret_cast<const float4*>(b_dyn)[tid];
        reinterpret_cast<float4*>(p_gn)[tid]   = reinterpret_cast<const float4*>(g_ndyn)[tid];
        reinterpret_cast<float4*>(p_bn)[tid]   = reinterpret_cast<const float4*>(b_ndyn)[tid];
        reinterpret_cast<float4*>(p_bq)[tid]   = reinterpret_cast<const float4*>(bq)[tid];
        reinterpret_cast<float4*>(p_bk)[tid]   = reinterpret_cast<const float4*>(bk)[tid];
    }
    __syncthreads();

    float acc[4][8];
    // ---- h0 = h_dyn @ W_dyn ----
    gemm_acc<256>(sm_hd, 512, 512, W_dyn, sm_wt, acc, tid);
    {
        const int tc = tid & 31, tok0 = (tid >> 5) * 4, col0 = tc * 8;
#pragma unroll
        for (int t = 0; t < 4; t++) {
            float s = 0.f, s2 = 0.f;
#pragma unroll
            for (int j = 0; j < 8; j++) {
                float v = acc[t][j] + p_bdyn[col0 + j];
                acc[t][j] = v; s += v; s2 += v * v;
            }
            float* h0p = g_h0 + (size_t)(row0 + tok0 + t) * DM + col0;
            reinterpret_cast<float4*>(h0p)[0] = make_float4(acc[t][0], acc[t][1], acc[t][2], acc[t][3]);
            reinterpret_cast<float4*>(h0p)[1] = make_float4(acc[t][4], acc[t][5], acc[t][6], acc[t][7]);
#pragma unroll
            for (int off = 16; off; off >>= 1) {
                s  += __shfl_xor_sync(0xffffffffu, s,  off);
                s2 += __shfl_xor_sync(0xffffffffu, s2, off);
            }
            float mean = s * (1.f / 256.f);
            float var  = s2 * (1.f / 256.f) - mean * mean;
            float rstd = rsqrtf(var + LN_EPS);
#pragma unroll
            for (int j = 0; j < 8; j++)
                sm_h[(tok0 + t) * DM + col0 + j] =
                    (acc[t][j] - mean) * rstd * p_gn[col0 + j] + p_bn[col0 + j];
        }
    }
    __syncthreads();

    // ---- q = h_ln @ Wq + bq ----
    gemm_acc<256>(sm_h, 256, 256, Wq, sm_wt, acc, tid);
    {
        const int tc = tid & 31, tok0 = (tid >> 5) * 4, col0 = tc * 8;
#pragma unroll
        for (int t = 0; t < 4; t++)
#pragma unroll
            for (int j = 0; j < 8; j++)
                sm_q[(tok0 + t) * DM + col0 + j] = acc[t][j] + p_bq[col0 + j];
    }
    __syncthreads();

    // ---- u[b,j,h] via staged Wk tiles ----
    for (int jt = 0; jt < 16; jt++) {
        const float4* src = reinterpret_cast<const float4*>(Wk + jt * 16 * DM);
        for (int f = tid; f < 1024; f += 256) {
            int r = f >> 6, c4 = f & 63;
            *reinterpret_cast<float4*>(sm_wt + r * WT_STRIDE + c4 * 4) = src[f];
        }
        __syncthreads();
        const int jl = tid & 15;
#pragma unroll
        for (int rr = 0; rr < 2; rr++) {
            const int r = (tid >> 4) + rr * 16;
            float ua[4];
#pragma unroll
            for (int h = 0; h < 4; h++) {
                float a = 0.f;
#pragma unroll
                for (int d4 = 0; d4 < 16; d4++) {
                    float4 qv = *reinterpret_cast<const float4*>(sm_q + r * DM + h * 64 + d4 * 4);
                    float4 wv = *reinterpret_cast<const float4*>(sm_wt + jl * WT_STRIDE + h * 64 + d4 * 4);
                    a += qv.x * wv.x + qv.y * wv.y + qv.z * wv.z + qv.w * wv.w;
                }
                ua[h] = a;
            }
            *reinterpret_cast<float4*>(g_u + (size_t)(row0 + r) * (DM * NH) + (jt * 16 + jl) * 4) =
                make_float4(ua[0], ua[1], ua[2], ua[3]);
        }
        __syncthreads();
    }

    // ---- qbk[b,h] ----
    if (tid < 128) {
        const int r = tid >> 2, h = tid & 3;
        float a = 0.f;
#pragma unroll
        for (int d = 0; d < 64; d++)
            a += sm_q[r * DM + h * 64 + d] * p_bk[h * 64 + d];
        g_qbk[(size_t)(row0 + r) * 4 + h] = a;
    }
}

// ============================================================
// Kernel 2: one block per batch row b. Full fused token path.
// ============================================================
__global__ void __launch_bounds__(512, 1) k2(
    const float* __restrict__ x_stat,
    const float* __restrict__ W_stat, const float* __restrict__ b_stat,
    const float* __restrict__ g_nstat, const float* __restrict__ b_nstat,
    const float* __restrict__ Wv, const float* __restrict__ bv,
    const float* __restrict__ g_mlp, const float* __restrict__ b_mlp,
    const float* __restrict__ W1, const float* __restrict__ b1,
    const float* __restrict__ W2, const float* __restrict__ b2,
    const float* __restrict__ Wo, const float* __restrict__ bo,
    const float* __restrict__ res_scale_p,
    float* __restrict__ out)
{
    extern __shared__ float sm[];
    float* A    = sm;                      // 64*260
    float* Bb   = A   + 64 * AST;          // 64*260
    float* xs   = Bb  + 64 * AST;          // 64*64
    float* Wt   = xs  + 64 * 64;           // 16*260
    float* us   = Wt  + 16 * WT_STRIDE;    // 1024 : u[j*4+h]
    float* pb   = us  + 1024;              // 10*256 params (see order below)
    float* wsm  = pb  + 10 * 256;          // 256 : w[h*64+k]
    float* zsm  = wsm + 256;               // 256
    float* ssum = zsm + 256;               // 8
    float* qbks = ssum + 8;                // 8

    const int tid = threadIdx.x;
    const int b   = blockIdx.x;

    // ---- cooperative loads ----
    {
        const float4* src = reinterpret_cast<const float4*>(x_stat + (size_t)b * 64 * 64);
        for (int f = tid; f < 1024; f += 512) reinterpret_cast<float4*>(xs)[f] = src[f];
        if (tid < 256)
            reinterpret_cast<float4*>(us)[tid] =
                reinterpret_cast<const float4*>(g_u + (size_t)b * 1024)[tid];
        if (tid < 64) {
            reinterpret_cast<float4*>(pb + 0 * 256)[tid] = reinterpret_cast<const float4*>(b_stat)[tid];
            reinterpret_cast<float4*>(pb + 1 * 256)[tid] = reinterpret_cast<const float4*>(g_nstat)[tid];
            reinterpret_cast<float4*>(pb + 2 * 256)[tid] = reinterpret_cast<const float4*>(b_nstat)[tid];
            reinterpret_cast<float4*>(pb + 3 * 256)[tid] = reinterpret_cast<const float4*>(bv)[tid];
            reinterpret_cast<float4*>(pb + 4 * 256)[tid] = reinterpret_cast<const float4*>(g_mlp)[tid];
            reinterpret_cast<float4*>(pb + 5 * 256)[tid] = reinterpret_cast<const float4*>(b_mlp)[tid];
            reinterpret_cast<float4*>(pb + 6 * 256)[tid] = reinterpret_cast<const float4*>(b1)[tid];
            reinterpret_cast<float4*>(pb + 7 * 256)[tid] = reinterpret_cast<const float4*>(b2)[tid];
            reinterpret_cast<float4*>(pb + 8 * 256)[tid] = reinterpret_cast<const float4*>(bo)[tid];
            reinterpret_cast<float4*>(pb + 9 * 256)[tid] =
                reinterpret_cast<const float4*>(g_h0 + (size_t)b * 256)[tid];
        }
        if (tid < 4) qbks[tid] = g_qbk[(size_t)b * 4 + tid];
    }
    __syncthreads();

    float acc[4][8];

    // ---- S1: s = x_stat @ W_stat + b_stat ; LN -> A ----
    gemm_acc<512>(xs, 64, 64, W_stat, Wt, acc, tid);
    epi_ln(acc, pb + 0 * 256, pb + 1 * 256, pb + 2 * 256, A, AST, tid);
    __syncthreads();

    // ---- logits / sigmoid / normalize / w_mean ----
    if (tid < 256) {
        const int k = tid >> 2, h = tid & 3;
        float a = qbks[h];
        const float* ar = A + k * AST;
#pragma unroll 4
        for (int j = 0; j < 256; j++) a += ar[j] * us[j * 4 + h];
        float lg = a * SCALE;
        wsm[h * 64 + k] = 1.f / (1.f + expf(-lg));
    }
    __syncthreads();
    if (tid < 4) {
        float s = 0.f;
        for (int k = 0; k < 64; k++) s += wsm[tid * 64 + k];
        ssum[tid] = s + 1e-6f;
    }
    __syncthreads();
    if (tid < 256) wsm[tid] = wsm[tid] / ssum[tid >> 6];
    __syncthreads();
    if (tid < 64)
        out[(size_t)B_ROWS * DM + (size_t)b * 64 + tid] =
            0.25f * (wsm[tid] + wsm[64 + tid] + wsm[128 + tid] + wsm[192 + tid]);

    // ---- S2: v = A @ Wv + bv ; LN(g_mlp) -> Bb ----
    gemm_acc<512>(A, AST, 256, Wv, Wt, acc, tid);
    epi_ln(acc, pb + 3 * 256, pb + 4 * 256, pb + 5 * 256, Bb, AST, tid);
    __syncthreads();

    // ---- S3: t = gelu(Bb @ W1 + b1) -> A ----
    gemm_acc<512>(Bb, AST, 256, W1, Wt, acc, tid);
    {
        const int tc = tid & 31, tok0 = (tid >> 5) * 4, col0 = tc * 8;
#pragma unroll
        for (int t = 0; t < 4; t++)
#pragma unroll
            for (int j = 0; j < 8; j++) {
                float x = acc[t][j] + pb[6 * 256 + col0 + j];
                A[(tok0 + t) * AST + col0 + j] = 0.5f * x * (1.f + erff(x * 0.70710678118f));
            }
    }
    __syncthreads();

    // ---- S4: vtok = A @ W2 + b2 -> Bb ----
    gemm_acc<512>(A, AST, 256, W2, Wt, acc, tid);
    {
        const int tc = tid & 31, tok0 = (tid >> 5) * 4, col0 = tc * 8;
#pragma unroll
        for (int t = 0; t < 4; t++)
#pragma unroll
            for (int j = 0; j < 8; j++)
                Bb[(tok0 + t) * AST + col0 + j] = acc[t][j] + pb[7 * 256 + col0 + j];
    }
    __syncthreads();

    // ---- z[d] = sum_k w[h(d),k] * vtok[k,d] ----
    if (tid < 256) {
        const int d = tid, h = d >> 6;
        float a = 0.f;
        const float* wr = wsm + h * 64;
#pragma unroll 8
        for (int k = 0; k < 64; k++) a += wr[k] * Bb[k * AST + d];
        zsm[d] = a;
    }
    __syncthreads();

    // ---- c = z @ Wo + bo ; out = h0 + res_scale*c ----
    if (tid < 256) {
        const int d = tid;
        float a = 0.f;
#pragma unroll 8
        for (int i = 0; i < 256; i++) a += zsm[i] * Wo[i * DM + d];
        float rs = *res_scale_p;
        out[(size_t)b * DM + d] = pb[9 * 256 + d] + rs * (a + pb[8 * 256 + d]);
    }
}

// ============================================================
extern "C" void kernel_launch(void* const* d_in, const int* in_sizes, int n_in,
                              void* d_out, int out_size)
{
    const float* h_dyn   = (const float*)d_in[0];
    const float* x_stat  = (const float*)d_in[1];
    const float* W_dyn   = (const float*)d_in[2];
    const float* b_dyn   = (const float*)d_in[3];
    const float* W_stat  = (const float*)d_in[4];
    const float* b_stat  = (const float*)d_in[5];
    const float* g_ndyn  = (const float*)d_in[6];
    const float* b_ndyn  = (const float*)d_in[7];
    const float* g_nstat = (const float*)d_in[8];
    const float* b_nstat = (const float*)d_in[9];
    const float* Wq      = (const float*)d_in[10];
    const float* bq      = (const float*)d_in[11];
    const float* Wk      = (const float*)d_in[12];
    const float* bk      = (const float*)d_in[13];
    const float* Wv      = (const float*)d_in[14];
    const float* bv      = (const float*)d_in[15];
    const float* g_mlp   = (const float*)d_in[16];
    const float* b_mlp   = (const float*)d_in[17];
    const float* W1      = (const float*)d_in[18];
    const float* b1      = (const float*)d_in[19];
    const float* W2      = (const float*)d_in[20];
    const float* b2      = (const float*)d_in[21];
    const float* Wo      = (const float*)d_in[22];
    const float* bo      = (const float*)d_in[23];
    const float* res_sc  = (const float*)d_in[24];
    float* out = (float*)d_out;

    const int SMEM1 = (32 * 512 + 32 * 256 + 32 * 256 + 16 * WT_STRIDE + 5 * 256) * 4;
    const int SMEM2 = (64 * AST * 2 + 64 * 64 + 16 * WT_STRIDE + 1024 + 10 * 256 + 256 + 256 + 16) * 4;

    cudaFuncSetAttribute(k1, cudaFuncAttributeMaxDynamicSharedMemorySize, SMEM1);
    cudaFuncSetAttribute(k2, cudaFuncAttributeMaxDynamicSharedMemorySize, SMEM2);

    k1<<<B_ROWS / 32, 256, SMEM1>>>(h_dyn, W_dyn, b_dyn, g_ndyn, b_ndyn, Wq, bq, Wk, bk);
    k2<<<B_ROWS, 512, SMEM2>>>(x_stat, W_stat, b_stat, g_nstat, b_nstat,
                               Wv, bv, g_mlp, b_mlp, W1, b1, W2, b2, Wo, bo,
                               res_sc, out);
}

// round 8
// speedup vs baseline: 3.0723x; 3.0722x over previous
#include <cuda_runtime.h>
#include <cuda_bf16.h>
#include <math.h>
#include <stdint.h>

#define B_ROWS 4096
#define DM     256
#define DDYN   512
#define SCALE  0.125f
#define LN_EPS 1e-5f
#define WT_STRIDE 260

// ---------------- device scratch ----------------
__device__ float g_h0 [B_ROWS * DM];
__device__ float g_u  [B_ROWS * DM * 4];
__device__ float g_qbk[B_ROWS * 4];
// 13 chunks (Wstat 1, Wv 4, W1 4, W2 4), each [n=256][k=64] bf16 swizzled = 32KB
__device__ uint4 g_Bhi[13 * 2048];
__device__ uint4 g_Blo[13 * 2048];

// ---------------- mma.sync bf16 (sm_80+ PTX; no 'a' target needed) ----------------
__device__ __forceinline__ void mma_bf16(float* d, const unsigned* a, unsigned b0, unsigned b1) {
    asm volatile("mma.sync.aligned.m16n8k16.row.col.f32.bf16.bf16.f32 "
        "{%0,%1,%2,%3}, {%4,%5,%6,%7}, {%8,%9}, {%0,%1,%2,%3};"
        : "+f"(d[0]), "+f"(d[1]), "+f"(d[2]), "+f"(d[3])
        : "r"(a[0]), "r"(a[1]), "r"(a[2]), "r"(a[3]), "r"(b0), "r"(b1));
}

// A smem layout: blocked atoms 8 rows x 64 cols (1KB), atom = (row>>3) + (col>>6)*16,
// byte = atom*1024 + (row&7)*128 + (((col&63)*2) ^ ((row&7)<<4))
__device__ __forceinline__ void storeA2(char* Ah, char* Al, int row, int col,
                                        float v0, float v1) {
    unsigned byte = ((unsigned)(row >> 3) << 10) + ((unsigned)(col >> 6) << 14)
                  + ((unsigned)(row & 7) << 7)
                  + ((((unsigned)(col & 63)) * 2u) ^ (((unsigned)(row & 7)) << 4));
    __nv_bfloat16 h0 = __float2bfloat16(v0), h1 = __float2bfloat16(v1);
    *(unsigned*)(Ah + byte) = (unsigned)__bfloat16_as_ushort(h0) |
                              ((unsigned)__bfloat16_as_ushort(h1) << 16);
    __nv_bfloat16 l0 = __float2bfloat16(v0 - __bfloat162float(h0));
    __nv_bfloat16 l1 = __float2bfloat16(v1 - __bfloat162float(h1));
    *(unsigned*)(Al + byte) = (unsigned)__bfloat16_as_ushort(l0) |
                              ((unsigned)__bfloat16_as_ushort(l1) << 16);
}

// ---------------- k0: weights -> [n][k] transposed, split, swizzled images ----------------
__global__ void k0(const float* __restrict__ Ws, const float* __restrict__ Wv,
                   const float* __restrict__ W1, const float* __restrict__ W2) {
    const int c = blockIdx.x, n = threadIdx.x;
    const float* W; int kc;
    if (c == 0)      { W = Ws; kc = 0; }
    else if (c <= 4) { W = Wv; kc = c - 1; }
    else if (c <= 8) { W = W1; kc = c - 5; }
    else             { W = W2; kc = c - 9; }
    char* bh = (char*)(g_Bhi + (size_t)c * 2048);
    char* bl = (char*)(g_Blo + (size_t)c * 2048);
    const unsigned nb = (unsigned)n * 128u;
    const unsigned nm = ((unsigned)n & 7u) << 4;
    for (int k = 0; k < 64; k++) {
        float v = W[(size_t)(kc * 64 + k) * 256 + n];
        __nv_bfloat16 h = __float2bfloat16(v);
        __nv_bfloat16 l = __float2bfloat16(v - __bfloat162float(h));
        unsigned off = nb + (((unsigned)k * 2u) ^ nm);
        *(__nv_bfloat16*)(bh + off) = h;
        *(__nv_bfloat16*)(bl + off) = l;
    }
}

// ---------------- k1: fp32 path (unchanged from best passing kernel) ----------------
template<int NTHREADS>
__device__ __forceinline__ void gemm_acc(
    const float* __restrict__ Asm, int astride, int kdim,
    const float* __restrict__ Wg, float* __restrict__ Wt,
    float acc[4][8], int tid)
{
#pragma unroll
    for (int t = 0; t < 4; t++)
#pragma unroll
        for (int j = 0; j < 8; j++) acc[t][j] = 0.f;
    const int tc = tid & 31, tok0 = (tid >> 5) * 4, col0 = tc * 8;
    const int nkt = kdim >> 4;
    for (int kt = 0; kt < nkt; ++kt) {
        const float4* src = reinterpret_cast<const float4*>(Wg + kt * 16 * DM);
#pragma unroll
        for (int f = tid; f < 1024; f += NTHREADS) {
            int row = f >> 6, c4 = f & 63;
            *reinterpret_cast<float4*>(Wt + row * WT_STRIDE + c4 * 4) = src[f];
        }
        __syncthreads();
#pragma unroll
        for (int kk4 = 0; kk4 < 4; ++kk4) {
            const int kbase = kt * 16 + kk4 * 4;
            float a_[4][4];
#pragma unroll
            for (int t = 0; t < 4; t++) {
                float4 v = *reinterpret_cast<const float4*>(Asm + (tok0 + t) * astride + kbase);
                a_[t][0]=v.x; a_[t][1]=v.y; a_[t][2]=v.z; a_[t][3]=v.w;
            }
#pragma unroll
            for (int r = 0; r < 4; r++) {
                const float4 w0 = *reinterpret_cast<const float4*>(Wt + (kk4*4+r)*WT_STRIDE + col0);
                const float4 w1 = *reinterpret_cast<const float4*>(Wt + (kk4*4+r)*WT_STRIDE + col0 + 4);
                float w[8] = {w0.x,w0.y,w0.z,w0.w,w1.x,w1.y,w1.z,w1.w};
#pragma unroll
                for (int t = 0; t < 4; t++) {
                    const float a = a_[t][r];
#pragma unroll
                    for (int j = 0; j < 8; j++) acc[t][j] = fmaf(a, w[j], acc[t][j]);
                }
            }
        }
        __syncthreads();
    }
}

__global__ void __launch_bounds__(256, 1) k1(
    const float* __restrict__ h_dyn, const float* __restrict__ W_dyn,
    const float* __restrict__ b_dyn, const float* __restrict__ g_ndyn,
    const float* __restrict__ b_ndyn, const float* __restrict__ Wq,
    const float* __restrict__ bq, const float* __restrict__ Wk,
    const float* __restrict__ bk)
{
    extern __shared__ float sm[];
    float* sm_hd  = sm;
    float* sm_h   = sm_hd + 32 * 512;
    float* sm_q   = sm_h  + 32 * 256;
    float* sm_wt  = sm_q  + 32 * 256;
    float* p_bdyn = sm_wt + 16 * WT_STRIDE;
    float* p_gn = p_bdyn + 256; float* p_bn = p_gn + 256;
    float* p_bq = p_bn + 256;   float* p_bk = p_bq + 256;

    const int tid = threadIdx.x;
    const int row0 = blockIdx.x * 32;
    {
        const float4* src = reinterpret_cast<const float4*>(h_dyn + (size_t)row0 * DDYN);
        for (int f = tid; f < 4096; f += 256) reinterpret_cast<float4*>(sm_hd)[f] = src[f];
    }
    if (tid < 64) {
        reinterpret_cast<float4*>(p_bdyn)[tid] = reinterpret_cast<const float4*>(b_dyn)[tid];
        reinterpret_cast<float4*>(p_gn)[tid]   = reinterpret_cast<const float4*>(g_ndyn)[tid];
        reinterpret_cast<float4*>(p_bn)[tid]   = reinterpret_cast<const float4*>(b_ndyn)[tid];
        reinterpret_cast<float4*>(p_bq)[tid]   = reinterpret_cast<const float4*>(bq)[tid];
        reinterpret_cast<float4*>(p_bk)[tid]   = reinterpret_cast<const float4*>(bk)[tid];
    }
    __syncthreads();

    float acc[4][8];
    gemm_acc<256>(sm_hd, 512, 512, W_dyn, sm_wt, acc, tid);
    {
        const int tc = tid & 31, tok0 = (tid >> 5) * 4, col0 = tc * 8;
#pragma unroll
        for (int t = 0; t < 4; t++) {
            float s = 0.f, s2 = 0.f;
#pragma unroll
            for (int j = 0; j < 8; j++) {
                float v = acc[t][j] + p_bdyn[col0 + j];
                acc[t][j] = v; s += v; s2 += v * v;
            }
            float* h0p = g_h0 + (size_t)(row0 + tok0 + t) * DM + col0;
            reinterpret_cast<float4*>(h0p)[0] = make_float4(acc[t][0],acc[t][1],acc[t][2],acc[t][3]);
            reinterpret_cast<float4*>(h0p)[1] = make_float4(acc[t][4],acc[t][5],acc[t][6],acc[t][7]);
#pragma unroll
            for (int off = 16; off; off >>= 1) {
                s  += __shfl_xor_sync(0xffffffffu, s,  off);
                s2 += __shfl_xor_sync(0xffffffffu, s2, off);
            }
            float mean = s * (1.f/256.f);
            float rstd = rsqrtf(s2 * (1.f/256.f) - mean*mean + LN_EPS);
#pragma unroll
            for (int j = 0; j < 8; j++)
                sm_h[(tok0+t)*DM + col0+j] = (acc[t][j]-mean)*rstd*p_gn[col0+j] + p_bn[col0+j];
        }
    }
    __syncthreads();

    gemm_acc<256>(sm_h, 256, 256, Wq, sm_wt, acc, tid);
    {
        const int tc = tid & 31, tok0 = (tid >> 5) * 4, col0 = tc * 8;
#pragma unroll
        for (int t = 0; t < 4; t++)
#pragma unroll
            for (int j = 0; j < 8; j++)
                sm_q[(tok0+t)*DM + col0+j] = acc[t][j] + p_bq[col0+j];
    }
    __syncthreads();

    for (int jt = 0; jt < 16; jt++) {
        const float4* src = reinterpret_cast<const float4*>(Wk + jt * 16 * DM);
        for (int f = tid; f < 1024; f += 256) {
            int r = f >> 6, c4 = f & 63;
            *reinterpret_cast<float4*>(sm_wt + r * WT_STRIDE + c4 * 4) = src[f];
        }
        __syncthreads();
        const int jl = tid & 15;
#pragma unroll
        for (int rr = 0; rr < 2; rr++) {
            const int r = (tid >> 4) + rr * 16;
            float ua[4];
#pragma unroll
            for (int h = 0; h < 4; h++) {
                float a = 0.f;
#pragma unroll
                for (int d4 = 0; d4 < 16; d4++) {
                    float4 qv = *reinterpret_cast<const float4*>(sm_q + r*DM + h*64 + d4*4);
                    float4 wv = *reinterpret_cast<const float4*>(sm_wt + jl*WT_STRIDE + h*64 + d4*4);
                    a += qv.x*wv.x + qv.y*wv.y + qv.z*wv.z + qv.w*wv.w;
                }
                ua[h] = a;
            }
            *reinterpret_cast<float4*>(g_u + (size_t)(row0+r)*1024 + (jt*16+jl)*4) =
                make_float4(ua[0], ua[1], ua[2], ua[3]);
        }
        __syncthreads();
    }
    if (tid < 128) {
        const int r = tid >> 2, h = tid & 3;
        float a = 0.f;
#pragma unroll
        for (int d = 0; d < 64; d++) a += sm_q[r*DM + h*64 + d] * p_bk[h*64 + d];
        g_qbk[(size_t)(row0+r)*4 + h] = a;
    }
}

// ---------------- k2m: HMMA fused token path, 2 batch rows / CTA ----------------
// smem byte offsets
#define O_AH   0         // 65536  A hi (128x256 bf16, blocked SW128)
#define O_AL   65536     // 65536  A lo
#define O_BH   131072    // 32768  B chunk hi [256][64]
#define O_BL   163840    // 32768  B chunk lo
#define O_PB   196608    // 9*256 params
#define O_US   205824    // 2048 floats: u for 2 rows
#define O_H0   214016    // 512 floats
#define O_PS   216064    // 128*4*2 floats: LN partials
#define O_LG   220160    // 8192: logit partials [row][wn][h]; reused as zs [2][256]
#define O_WN   228352    // 512 floats: weights [row][h]
#define O_TAIL 230400    // qbk(8) + ssum(8)
#define SMEM2  230464

__device__ __forceinline__ void gemm_tc(float acc[2][8][4],
    const char* Ah, const char* Al, char* Bh, char* Bl,
    int c0, int nc, int wm, int wn4, int lane, int tid)
{
#pragma unroll
    for (int mt = 0; mt < 2; mt++)
#pragma unroll
        for (int nt = 0; nt < 8; nt++)
#pragma unroll
            for (int q = 0; q < 4; q++) acc[mt][nt][q] = 0.f;

    const int g8 = lane >> 2, tp = lane & 3;
    unsigned arb[4];
#pragma unroll
    for (int i = 0; i < 4; i++) {
        int row = wm * 32 + (i >> 1) * 16 + (i & 1) * 8 + g8;
        arb[i] = ((unsigned)(row >> 3) << 10) | ((unsigned)(row & 7) << 7);
    }
    const unsigned am = (unsigned)g8 << 4;
    const unsigned bbase = (unsigned)((wn4 * 64 + g8) * 128);

    for (int kc = 0; kc < nc; kc++) {
        const uint4* gh = g_Bhi + (size_t)(c0 + kc) * 2048;
        const uint4* gl = g_Blo + (size_t)(c0 + kc) * 2048;
#pragma unroll
        for (int i = tid; i < 2048; i += 512) {
            ((uint4*)Bh)[i] = gh[i]; ((uint4*)Bl)[i] = gl[i];
        }
        __syncthreads();
        const unsigned kcb = (unsigned)kc << 14;
#pragma unroll
        for (int ks = 0; ks < 4; ks++) {
            const unsigned cb0 = (unsigned)(ks * 32 + tp * 4);
            unsigned ah[2][4], al[2][4];
#pragma unroll
            for (int mt = 0; mt < 2; mt++)
#pragma unroll
                for (int rh = 0; rh < 2; rh++) {
                    unsigned a0 = kcb + arb[mt*2+rh] + (cb0 ^ am);
                    unsigned a1 = kcb + arb[mt*2+rh] + ((cb0 + 16u) ^ am);
                    ah[mt][rh]     = *(const unsigned*)(Ah + a0);
                    ah[mt][rh + 2] = *(const unsigned*)(Ah + a1);
                    al[mt][rh]     = *(const unsigned*)(Al + a0);
                    al[mt][rh + 2] = *(const unsigned*)(Al + a1);
                }
#pragma unroll
            for (int nt = 0; nt < 8; nt++) {
                unsigned bo0 = bbase + (unsigned)(nt * 1024) + (cb0 ^ am);
                unsigned bo1 = bbase + (unsigned)(nt * 1024) + ((cb0 + 16u) ^ am);
                unsigned bh0 = *(const unsigned*)(Bh + bo0);
                unsigned bh1 = *(const unsigned*)(Bh + bo1);
                unsigned bl0 = *(const unsigned*)(Bl + bo0);
                unsigned bl1 = *(const unsigned*)(Bl + bo1);
#pragma unroll
                for (int mt = 0; mt < 2; mt++) {
                    mma_bf16(acc[mt][nt], ah[mt], bh0, bh1);
                    mma_bf16(acc[mt][nt], ah[mt], bl0, bl1);
                    mma_bf16(acc[mt][nt], al[mt], bh0, bh1);
                }
            }
        }
        __syncthreads();
    }
}

// LN epilogue on register fragments; optional logit partials (S1)
__device__ __forceinline__ void epi_ln_m(float acc[2][8][4],
    const float* bias, const float* gg, const float* bb,
    char* Ah, char* Al, float* ps, const float* us, float* lg,
    int wm, int wn4, int lane, bool do_logits)
{
    const int g8 = lane >> 2, tp = lane & 3;
    float s[4] = {0,0,0,0}, s2[4] = {0,0,0,0};
#pragma unroll
    for (int mt = 0; mt < 2; mt++)
#pragma unroll
        for (int nt = 0; nt < 8; nt++) {
            int C = wn4 * 64 + nt * 8 + tp * 2;
            float b0v = bias[C], b1v = bias[C + 1];
            float v0 = acc[mt][nt][0] + b0v, v1 = acc[mt][nt][1] + b1v;
            float v2 = acc[mt][nt][2] + b0v, v3 = acc[mt][nt][3] + b1v;
            acc[mt][nt][0]=v0; acc[mt][nt][1]=v1; acc[mt][nt][2]=v2; acc[mt][nt][3]=v3;
            s[mt*2]   += v0 + v1;  s2[mt*2]   += v0*v0 + v1*v1;
            s[mt*2+1] += v2 + v3;  s2[mt*2+1] += v2*v2 + v3*v3;
        }
#pragma unroll
    for (int off = 1; off <= 2; off <<= 1)
#pragma unroll
        for (int i = 0; i < 4; i++) {
            s[i]  += __shfl_xor_sync(0xffffffffu, s[i],  off);
            s2[i] += __shfl_xor_sync(0xffffffffu, s2[i], off);
        }
    if (tp == 0) {
#pragma unroll
        for (int i = 0; i < 4; i++) {
            int row = wm*32 + (i>>1)*16 + (i&1)*8 + g8;
            ps[(row*4 + wn4)*2]     = s[i];
            ps[(row*4 + wn4)*2 + 1] = s2[i];
        }
    }
    __syncthreads();
    float mean[4], rstd[4];
#pragma unroll
    for (int i = 0; i < 4; i++) {
        int row = wm*32 + (i>>1)*16 + (i&1)*8 + g8;
        float ss = 0.f, ss2 = 0.f;
#pragma unroll
        for (int x = 0; x < 4; x++) { ss += ps[(row*4+x)*2]; ss2 += ps[(row*4+x)*2+1]; }
        mean[i] = ss * (1.f/256.f);
        rstd[i] = rsqrtf(ss2 * (1.f/256.f) - mean[i]*mean[i] + LN_EPS);
    }
    float la[4][4];
    if (do_logits)
#pragma unroll
        for (int i = 0; i < 4; i++)
#pragma unroll
            for (int h = 0; h < 4; h++) la[i][h] = 0.f;
    const int half = wm >> 1;
#pragma unroll
    for (int mt = 0; mt < 2; mt++)
#pragma unroll
        for (int nt = 0; nt < 8; nt++) {
            int C = wn4 * 64 + nt * 8 + tp * 2;
            float g0 = gg[C], g1 = gg[C+1], e0 = bb[C], e1 = bb[C+1];
#pragma unroll
            for (int rh = 0; rh < 2; rh++) {
                int i = mt*2 + rh;
                int row = wm*32 + mt*16 + rh*8 + g8;
                float n0 = (acc[mt][nt][rh*2]   - mean[i]) * rstd[i] * g0 + e0;
                float n1 = (acc[mt][nt][rh*2+1] - mean[i]) * rstd[i] * g1 + e1;
                storeA2(Ah, Al, row, C, n0, n1);
                if (do_logits) {
                    float4 u0 = *(const float4*)(us + half*1024 + C*4);
                    float4 u1 = *(const float4*)(us + half*1024 + (C+1)*4);
                    la[i][0] += n0*u0.x + n1*u1.x;
                    la[i][1] += n0*u0.y + n1*u1.y;
                    la[i][2] += n0*u0.z + n1*u1.z;
                    la[i][3] += n0*u0.w + n1*u1.w;
                }
            }
        }
    if (do_logits) {
#pragma unroll
        for (int off = 1; off <= 2; off <<= 1)
#pragma unroll
            for (int i = 0; i < 4; i++)
#pragma unroll
                for (int h = 0; h < 4; h++)
                    la[i][h] += __shfl_xor_sync(0xffffffffu, la[i][h], off);
        if (tp == 0)
#pragma unroll
            for (int i = 0; i < 4; i++) {
                int row = wm*32 + (i>>1)*16 + (i&1)*8 + g8;
#pragma unroll
                for (int h = 0; h < 4; h++) lg[row*16 + wn4*4 + h] = la[i][h];
            }
    }
    __syncthreads();
}

__global__ void __launch_bounds__(512, 1) k2m(
    const float* __restrict__ x_stat,
    const float* __restrict__ b_stat, const float* __restrict__ g_nstat,
    const float* __restrict__ b_nstat, const float* __restrict__ bv,
    const float* __restrict__ g_mlp,  const float* __restrict__ b_mlp,
    const float* __restrict__ b1,     const float* __restrict__ b2,
    const float* __restrict__ bo,     const float* __restrict__ Wo,
    const float* __restrict__ res_scale_p, float* __restrict__ out)
{
    extern __shared__ char smc[];
    char*  Ah  = smc + O_AH;
    char*  Al  = smc + O_AL;
    char*  Bh  = smc + O_BH;
    char*  Bl  = smc + O_BL;
    float* pb  = (float*)(smc + O_PB);
    float* us  = (float*)(smc + O_US);
    float* h0s = (float*)(smc + O_H0);
    float* ps  = (float*)(smc + O_PS);
    float* lg  = (float*)(smc + O_LG);
    float* zs  = (float*)(smc + O_LG);   // reuse (zs only after S1 done)
    float* wns = (float*)(smc + O_WN);
    float* qbk = (float*)(smc + O_TAIL);
    float* ssm = (float*)(smc + O_TAIL + 32);

    const int tid = threadIdx.x, lane = tid & 31, w = tid >> 5;
    const int wm = w & 3, wn4 = w >> 2;
    const int g8 = lane >> 2, tp = lane & 3;
    const size_t b0 = (size_t)blockIdx.x * 2;

    // ---- cooperative loads ----
    for (int idx = tid; idx < 2048; idx += 512) {       // x_stat -> A split (128 rows x 64 cols)
        int rr = idx >> 4, c4 = (idx & 15) * 4;
        float4 v = *reinterpret_cast<const float4*>(
            x_stat + (b0 + (rr >> 6)) * 4096 + (size_t)(rr & 63) * 64 + c4);
        storeA2(Ah, Al, rr, c4,     v.x, v.y);
        storeA2(Ah, Al, rr, c4 + 2, v.z, v.w);
    }
    {
        int i = tid;
        if (i < 512)
            reinterpret_cast<float4*>(us)[i] =
                reinterpret_cast<const float4*>(g_u + b0 * 1024)[i];
    }
    if (tid < 64) {
        reinterpret_cast<float4*>(pb + 0*256)[tid] = reinterpret_cast<const float4*>(b_stat)[tid];
        reinterpret_cast<float4*>(pb + 1*256)[tid] = reinterpret_cast<const float4*>(g_nstat)[tid];
        reinterpret_cast<float4*>(pb + 2*256)[tid] = reinterpret_cast<const float4*>(b_nstat)[tid];
        reinterpret_cast<float4*>(pb + 3*256)[tid] = reinterpret_cast<const float4*>(bv)[tid];
        reinterpret_cast<float4*>(pb + 4*256)[tid] = reinterpret_cast<const float4*>(g_mlp)[tid];
        reinterpret_cast<float4*>(pb + 5*256)[tid] = reinterpret_cast<const float4*>(b_mlp)[tid];
        reinterpret_cast<float4*>(pb + 6*256)[tid] = reinterpret_cast<const float4*>(b1)[tid];
        reinterpret_cast<float4*>(pb + 7*256)[tid] = reinterpret_cast<const float4*>(b2)[tid];
        reinterpret_cast<float4*>(pb + 8*256)[tid] = reinterpret_cast<const float4*>(bo)[tid];
    }
    if (tid < 128)
        reinterpret_cast<float4*>(h0s)[tid] = reinterpret_cast<const float4*>(g_h0 + b0 * 256)[tid];
    if (tid < 8) qbk[tid] = g_qbk[b0 * 4 + tid];
    // (first gemm_tc starts with B copy + __syncthreads, covering these stores)

    float acc[2][8][4];

    // ---- S1: s = x_stat @ W_stat ; LN -> A ; logit partials ----
    gemm_tc(acc, Ah, Al, Bh, Bl, 0, 1, wm, wn4, lane, tid);
    epi_ln_m(acc, pb + 0*256, pb + 1*256, pb + 2*256, Ah, Al, ps, us, lg,
             wm, wn4, lane, true);

    // ---- logits -> sigmoid -> normalize -> w_mean ----
    {
        int row = tid >> 2, h = tid & 3;
        float lv = qbk[(row >> 6) * 4 + h];
#pragma unroll
        for (int x = 0; x < 4; x++) lv += lg[row*16 + x*4 + h];
        wns[tid] = 1.f / (1.f + expf(-lv * SCALE));
    }
    __syncthreads();
    if (tid < 8) {
        int half = tid >> 2, h = tid & 3;
        float sum = 0.f;
        for (int k = 0; k < 64; k++) sum += wns[(half*64 + k)*4 + h];
        ssm[tid] = sum + 1e-6f;
    }
    __syncthreads();
    {
        float v = wns[tid] / ssm[(tid >> 8) * 4 + (tid & 3)];
        wns[tid] = v;
    }
    __syncthreads();
    if (tid < 128)
        out[(size_t)B_ROWS * DM + (b0 + (tid >> 6)) * 64 + (tid & 63)] =
            0.25f * (wns[tid*4] + wns[tid*4+1] + wns[tid*4+2] + wns[tid*4+3]);
    __syncthreads();

    // ---- S2: v = s @ Wv ; LN(g_mlp) -> A ----
    gemm_tc(acc, Ah, Al, Bh, Bl, 1, 4, wm, wn4, lane, tid);
    epi_ln_m(acc, pb + 3*256, pb + 4*256, pb + 5*256, Ah, Al, ps, us, lg,
             wm, wn4, lane, false);

    // ---- S3: t = gelu(v @ W1 + b1) -> A ----
    gemm_tc(acc, Ah, Al, Bh, Bl, 5, 4, wm, wn4, lane, tid);
#pragma unroll
    for (int mt = 0; mt < 2; mt++)
#pragma unroll
        for (int nt = 0; nt < 8; nt++) {
            int C = wn4 * 64 + nt * 8 + tp * 2;
            float e0 = pb[6*256 + C], e1 = pb[6*256 + C + 1];
#pragma unroll
            for (int rh = 0; rh < 2; rh++) {
                int row = wm*32 + mt*16 + rh*8 + g8;
                float x0 = acc[mt][nt][rh*2]   + e0;
                float x1 = acc[mt][nt][rh*2+1] + e1;
                float n0 = 0.5f * x0 * (1.f + erff(x0 * 0.70710678118f));
                float n1 = 0.5f * x1 * (1.f + erff(x1 * 0.70710678118f));
                storeA2(Ah, Al, row, C, n0, n1);
            }
        }
    __syncthreads();

    // ---- S4: vtok = t @ W2 + b2 ; weighted column sums -> zs ----
    gemm_tc(acc, Ah, Al, Bh, Bl, 9, 4, wm, wn4, lane, tid);
    if (tid < 512) zs[tid] = 0.f;
    __syncthreads();
    {
        float z0[8], z1[8];
#pragma unroll
        for (int nt = 0; nt < 8; nt++) { z0[nt] = 0.f; z1[nt] = 0.f; }
#pragma unroll
        for (int mt = 0; mt < 2; mt++)
#pragma unroll
            for (int nt = 0; nt < 8; nt++) {
                int C = wn4 * 64 + nt * 8 + tp * 2;
                int hcol = C >> 6;
                float e0 = pb[7*256 + C], e1 = pb[7*256 + C + 1];
#pragma unroll
                for (int rh = 0; rh < 2; rh++) {
                    int row = wm*32 + mt*16 + rh*8 + g8;
                    float wf = wns[row*4 + hcol];
                    z0[nt] += (acc[mt][nt][rh*2]   + e0) * wf;
                    z1[nt] += (acc[mt][nt][rh*2+1] + e1) * wf;
                }
            }
#pragma unroll
        for (int off = 4; off <= 16; off <<= 1)
#pragma unroll
            for (int nt = 0; nt < 8; nt++) {
                z0[nt] += __shfl_xor_sync(0xffffffffu, z0[nt], off);
                z1[nt] += __shfl_xor_sync(0xffffffffu, z1[nt], off);
            }
        if (lane < 4) {
            int half = wm >> 1;
#pragma unroll
            for (int nt = 0; nt < 8; nt++) {
                int C = wn4 * 64 + nt * 8 + lane * 2;
                atomicAdd(&zs[half*256 + C],     z0[nt]);
                atomicAdd(&zs[half*256 + C + 1], z1[nt]);
            }
        }
    }
    __syncthreads();

    // ---- c = z @ Wo + bo ; out = h0 + rs*c ----
    {
        int half = tid >> 8, d = tid & 255;
        float a = 0.f;
        const float* zrow = zs + half * 256;
#pragma unroll 8
        for (int i = 0; i < 256; i++) a = fmaf(zrow[i], Wo[(size_t)i * 256 + d], a);
        float rs = *res_scale_p;
        out[(b0 + half) * 256 + d] = h0s[half*256 + d] + rs * (a + pb[8*256 + d]);
    }
}

// ============================================================
extern "C" void kernel_launch(void* const* d_in, const int* in_sizes, int n_in,
                              void* d_out, int out_size)
{
    const float* h_dyn   = (const float*)d_in[0];
    const float* x_stat  = (const float*)d_in[1];
    const float* W_dyn   = (const float*)d_in[2];
    const float* b_dyn   = (const float*)d_in[3];
    const float* W_stat  = (const float*)d_in[4];
    const float* b_stat  = (const float*)d_in[5];
    const float* g_ndyn  = (const float*)d_in[6];
    const float* b_ndyn  = (const float*)d_in[7];
    const float* g_nstat = (const float*)d_in[8];
    const float* b_nstat = (const float*)d_in[9];
    const float* Wq  = (const float*)d_in[10];
    const float* bq  = (const float*)d_in[11];
    const float* Wk  = (const float*)d_in[12];
    const float* bk  = (const float*)d_in[13];
    const float* Wv  = (const float*)d_in[14];
    const float* bv  = (const float*)d_in[15];
    const float* g_mlp = (const float*)d_in[16];
    const float* b_mlp = (const float*)d_in[17];
    const float* W1  = (const float*)d_in[18];
    const float* b1  = (const float*)d_in[19];
    const float* W2  = (const float*)d_in[20];
    const float* b2  = (const float*)d_in[21];
    const float* Wo  = (const float*)d_in[22];
    const float* bo  = (const float*)d_in[23];
    const float* res_sc = (const float*)d_in[24];
    float* out = (float*)d_out;

    const int SMEM1 = (32*512 + 32*256 + 32*256 + 16*WT_STRIDE + 5*256) * 4;
    cudaFuncSetAttribute(k1,  cudaFuncAttributeMaxDynamicSharedMemorySize, SMEM1);
    cudaFuncSetAttribute(k2m, cudaFuncAttributeMaxDynamicSharedMemorySize, SMEM2);

    k0<<<13, 256>>>(W_stat, Wv, W1, W2);
    k1<<<B_ROWS / 32, 256, SMEM1>>>(h_dyn, W_dyn, b_dyn, g_ndyn, b_ndyn, Wq, bq, Wk, bk);
    k2m<<<B_ROWS / 2, 512, SMEM2>>>(x_stat, b_stat, g_nstat, b_nstat, bv,
                                    g_mlp, b_mlp, b1, b2, bo, Wo, res_sc, out);
}

// round 9
// speedup vs baseline: 3.5420x; 1.1529x over previous
#include <cuda_runtime.h>
#include <cuda_bf16.h>
#include <math.h>
#include <stdint.h>

#define B_ROWS 4096
#define DM     256
#define DDYN   512
#define SCALE  0.125f
#define LN_EPS 1e-5f
#define WT_STRIDE 260
#define NCHUNK 26

// ---------------- device scratch ----------------
__device__ float g_h0 [B_ROWS * DM];
__device__ float g_u  [B_ROWS * DM * 4];
__device__ float g_qbk[B_ROWS * 4];
__device__ float g_z  [B_ROWS * DM];
// 26 chunks (Wstat 2, Wv 8, W1 8, W2 8): [256 n][128B row = 32k hi | 32k lo] swizzled
__device__ uint4 g_B[NCHUNK * 2048];

__device__ __forceinline__ uint32_t smem_u32(const void* p) {
    uint32_t a;
    asm("{ .reg .u64 t; cvta.to.shared.u64 t, %1; cvt.u32.u64 %0, t; }" : "=r"(a) : "l"(p));
    return a;
}

// ---------------- mma.sync bf16 (sm_80+ PTX) ----------------
__device__ __forceinline__ void mma_bf16(float* d, const unsigned* a, unsigned b0, unsigned b1) {
    asm volatile("mma.sync.aligned.m16n8k16.row.col.f32.bf16.bf16.f32 "
        "{%0,%1,%2,%3}, {%4,%5,%6,%7}, {%8,%9}, {%0,%1,%2,%3};"
        : "+f"(d[0]), "+f"(d[1]), "+f"(d[2]), "+f"(d[3])
        : "r"(a[0]), "r"(a[1]), "r"(a[2]), "r"(a[3]), "r"(b0), "r"(b1));
}

// A smem layout: blocked atoms 8 rows x 64 cols (1KB), atom = (row>>3) + (col>>6)*16
__device__ __forceinline__ void storeA2(char* Ah, char* Al, int row, int col,
                                        float v0, float v1) {
    unsigned byte = ((unsigned)(row >> 3) << 10) + ((unsigned)(col >> 6) << 14)
                  + ((unsigned)(row & 7) << 7)
                  + ((((unsigned)(col & 63)) * 2u) ^ (((unsigned)(row & 7)) << 4));
    __nv_bfloat16 h0 = __float2bfloat16(v0), h1 = __float2bfloat16(v1);
    *(unsigned*)(Ah + byte) = (unsigned)__bfloat16_as_ushort(h0) |
                              ((unsigned)__bfloat16_as_ushort(h1) << 16);
    __nv_bfloat16 l0 = __float2bfloat16(v0 - __bfloat162float(h0));
    __nv_bfloat16 l1 = __float2bfloat16(v1 - __bfloat162float(h1));
    *(unsigned*)(Al + byte) = (unsigned)__bfloat16_as_ushort(l0) |
                              ((unsigned)__bfloat16_as_ushort(l1) << 16);
}

// ---------------- k0: weights -> interleaved hi/lo swizzled chunk images ----------------
__global__ void k0(const float* __restrict__ Ws, const float* __restrict__ Wv,
                   const float* __restrict__ W1, const float* __restrict__ W2) {
    const int c = blockIdx.x, n = threadIdx.x;   // c: 0..25, n: 0..255
    const float* W; int kbase;
    if (c < 2)       { W = Ws; kbase = c * 32; }
    else if (c < 10) { W = Wv; kbase = (c - 2) * 32; }
    else if (c < 18) { W = W1; kbase = (c - 10) * 32; }
    else             { W = W2; kbase = (c - 18) * 32; }
    char* bp = (char*)(g_B + (size_t)c * 2048) + n * 128;
    const unsigned nm = ((unsigned)n & 7u) << 4;
    for (int kl = 0; kl < 32; kl++) {
        float v = W[(size_t)(kbase + kl) * 256 + n];
        __nv_bfloat16 h = __float2bfloat16(v);
        __nv_bfloat16 l = __float2bfloat16(v - __bfloat162float(h));
        *(__nv_bfloat16*)(bp + (((unsigned)kl * 2u) ^ nm))        = h;
        *(__nv_bfloat16*)(bp + ((64u + (unsigned)kl * 2u) ^ nm))  = l;
    }
}

// ---------------- fp32 tiled GEMM helper (k1, k3) ----------------
template<int NTHREADS>
__device__ __forceinline__ void gemm_acc(
    const float* __restrict__ Asm, int astride, int kdim,
    const float* __restrict__ Wg, float* __restrict__ Wt,
    float acc[4][8], int tid)
{
#pragma unroll
    for (int t = 0; t < 4; t++)
#pragma unroll
        for (int j = 0; j < 8; j++) acc[t][j] = 0.f;
    const int tc = tid & 31, tok0 = (tid >> 5) * 4, col0 = tc * 8;
    const int nkt = kdim >> 4;
    for (int kt = 0; kt < nkt; ++kt) {
        const float4* src = reinterpret_cast<const float4*>(Wg + kt * 16 * DM);
#pragma unroll
        for (int f = tid; f < 1024; f += NTHREADS) {
            int row = f >> 6, c4 = f & 63;
            *reinterpret_cast<float4*>(Wt + row * WT_STRIDE + c4 * 4) = src[f];
        }
        __syncthreads();
#pragma unroll
        for (int kk4 = 0; kk4 < 4; ++kk4) {
            const int kbase = kt * 16 + kk4 * 4;
            float a_[4][4];
#pragma unroll
            for (int t = 0; t < 4; t++) {
                float4 v = *reinterpret_cast<const float4*>(Asm + (tok0 + t) * astride + kbase);
                a_[t][0]=v.x; a_[t][1]=v.y; a_[t][2]=v.z; a_[t][3]=v.w;
            }
#pragma unroll
            for (int r = 0; r < 4; r++) {
                const float4 w0 = *reinterpret_cast<const float4*>(Wt + (kk4*4+r)*WT_STRIDE + col0);
                const float4 w1 = *reinterpret_cast<const float4*>(Wt + (kk4*4+r)*WT_STRIDE + col0 + 4);
                float w[8] = {w0.x,w0.y,w0.z,w0.w,w1.x,w1.y,w1.z,w1.w};
#pragma unroll
                for (int t = 0; t < 4; t++) {
                    const float a = a_[t][r];
#pragma unroll
                    for (int j = 0; j < 8; j++) acc[t][j] = fmaf(a, w[j], acc[t][j]);
                }
            }
        }
        __syncthreads();
    }
}

// ---------------- k1: fp32 path (unchanged) ----------------
__global__ void __launch_bounds__(256, 1) k1(
    const float* __restrict__ h_dyn, const float* __restrict__ W_dyn,
    const float* __restrict__ b_dyn, const float* __restrict__ g_ndyn,
    const float* __restrict__ b_ndyn, const float* __restrict__ Wq,
    const float* __restrict__ bq, const float* __restrict__ Wk,
    const float* __restrict__ bk)
{
    extern __shared__ float sm[];
    float* sm_hd  = sm;
    float* sm_h   = sm_hd + 32 * 512;
    float* sm_q   = sm_h  + 32 * 256;
    float* sm_wt  = sm_q  + 32 * 256;
    float* p_bdyn = sm_wt + 16 * WT_STRIDE;
    float* p_gn = p_bdyn + 256; float* p_bn = p_gn + 256;
    float* p_bq = p_bn + 256;   float* p_bk = p_bq + 256;

    const int tid = threadIdx.x;
    const int row0 = blockIdx.x * 32;
    {
        const float4* src = reinterpret_cast<const float4*>(h_dyn + (size_t)row0 * DDYN);
        for (int f = tid; f < 4096; f += 256) reinterpret_cast<float4*>(sm_hd)[f] = src[f];
    }
    if (tid < 64) {
        reinterpret_cast<float4*>(p_bdyn)[tid] = reinterpret_cast<const float4*>(b_dyn)[tid];
        reinterpret_cast<float4*>(p_gn)[tid]   = reinterpret_cast<const float4*>(g_ndyn)[tid];
        reinterpret_cast<float4*>(p_bn)[tid]   = reinterpret_cast<const float4*>(b_ndyn)[tid];
        reinterpret_cast<float4*>(p_bq)[tid]   = reinterpret_cast<const float4*>(bq)[tid];
        reinterpret_cast<float4*>(p_bk)[tid]   = reinterpret_cast<const float4*>(bk)[tid];
    }
    __syncthreads();

    float acc[4][8];
    gemm_acc<256>(sm_hd, 512, 512, W_dyn, sm_wt, acc, tid);
    {
        const int tc = tid & 31, tok0 = (tid >> 5) * 4, col0 = tc * 8;
#pragma unroll
        for (int t = 0; t < 4; t++) {
            float s = 0.f, s2 = 0.f;
#pragma unroll
            for (int j = 0; j < 8; j++) {
                float v = acc[t][j] + p_bdyn[col0 + j];
                acc[t][j] = v; s += v; s2 += v * v;
            }
            float* h0p = g_h0 + (size_t)(row0 + tok0 + t) * DM + col0;
            reinterpret_cast<float4*>(h0p)[0] = make_float4(acc[t][0],acc[t][1],acc[t][2],acc[t][3]);
            reinterpret_cast<float4*>(h0p)[1] = make_float4(acc[t][4],acc[t][5],acc[t][6],acc[t][7]);
#pragma unroll
            for (int off = 16; off; off >>= 1) {
                s  += __shfl_xor_sync(0xffffffffu, s,  off);
                s2 += __shfl_xor_sync(0xffffffffu, s2, off);
            }
            float mean = s * (1.f/256.f);
            float rstd = rsqrtf(s2 * (1.f/256.f) - mean*mean + LN_EPS);
#pragma unroll
            for (int j = 0; j < 8; j++)
                sm_h[(tok0+t)*DM + col0+j] = (acc[t][j]-mean)*rstd*p_gn[col0+j] + p_bn[col0+j];
        }
    }
    __syncthreads();

    gemm_acc<256>(sm_h, 256, 256, Wq, sm_wt, acc, tid);
    {
        const int tc = tid & 31, tok0 = (tid >> 5) * 4, col0 = tc * 8;
#pragma unroll
        for (int t = 0; t < 4; t++)
#pragma unroll
            for (int j = 0; j < 8; j++)
                sm_q[(tok0+t)*DM + col0+j] = acc[t][j] + p_bq[col0+j];
    }
    __syncthreads();

    for (int jt = 0; jt < 16; jt++) {
        const float4* src = reinterpret_cast<const float4*>(Wk + jt * 16 * DM);
        for (int f = tid; f < 1024; f += 256) {
            int r = f >> 6, c4 = f & 63;
            *reinterpret_cast<float4*>(sm_wt + r * WT_STRIDE + c4 * 4) = src[f];
        }
        __syncthreads();
        const int jl = tid & 15;
#pragma unroll
        for (int rr = 0; rr < 2; rr++) {
            const int r = (tid >> 4) + rr * 16;
            float ua[4];
#pragma unroll
            for (int h = 0; h < 4; h++) {
                float a = 0.f;
#pragma unroll
                for (int d4 = 0; d4 < 16; d4++) {
                    float4 qv = *reinterpret_cast<const float4*>(sm_q + r*DM + h*64 + d4*4);
                    float4 wv = *reinterpret_cast<const float4*>(sm_wt + jl*WT_STRIDE + h*64 + d4*4);
                    a += qv.x*wv.x + qv.y*wv.y + qv.z*wv.z + qv.w*wv.w;
                }
                ua[h] = a;
            }
            *reinterpret_cast<float4*>(g_u + (size_t)(row0+r)*1024 + (jt*16+jl)*4) =
                make_float4(ua[0], ua[1], ua[2], ua[3]);
        }
        __syncthreads();
    }
    if (tid < 128) {
        const int r = tid >> 2, h = tid & 3;
        float a = 0.f;
#pragma unroll
        for (int d = 0; d < 64; d++) a += sm_q[r*DM + h*64 + d] * p_bk[h*64 + d];
        g_qbk[(size_t)(row0+r)*4 + h] = a;
    }
}

// ---------------- k2m: HMMA fused token path, cp.async pipelined ----------------
#define O_AH   0
#define O_AL   65536
#define O_B0   131072
#define O_B1   163840
#define O_PB   196608
#define O_US   205824
#define O_H0   214016
#define O_PS   216064
#define O_LG   220160
#define O_WN   228352
#define O_TAIL 230400
#define SMEM2  230464

__device__ __forceinline__ void prefetch_chunk(char* buf, int g, int tid) {
    const char* src = (const char*)(g_B + (size_t)g * 2048);
    unsigned dst = smem_u32(buf);
#pragma unroll
    for (int i = 0; i < 4; i++) {
        int o = (tid + i * 512) * 16;
        asm volatile("cp.async.cg.shared.global [%0], [%1], 16;"
            :: "r"(dst + o), "l"(src + o) : "memory");
    }
    asm volatile("cp.async.commit_group;" ::: "memory");
}

__device__ __forceinline__ void gemm_tc(float acc[2][8][4],
    const char* Ah, const char* Al, char* B0, char* B1,
    int g0, int nc, int wm, int wn4, int lane, int tid)
{
#pragma unroll
    for (int mt = 0; mt < 2; mt++)
#pragma unroll
        for (int nt = 0; nt < 8; nt++)
#pragma unroll
            for (int q = 0; q < 4; q++) acc[mt][nt][q] = 0.f;

    const int g8 = lane >> 2, tp = lane & 3;
    unsigned arb[4];
#pragma unroll
    for (int i = 0; i < 4; i++) {
        int row = wm * 32 + (i >> 1) * 16 + (i & 1) * 8 + g8;
        arb[i] = ((unsigned)(row >> 3) << 10) | ((unsigned)(row & 7) << 7);
    }
    const unsigned am = (unsigned)g8 << 4;
    const unsigned brow = (unsigned)((wn4 * 64 + g8) * 128);

    for (int kc = 0; kc < nc; kc++) {
        const int g = g0 + kc;
        asm volatile("cp.async.wait_group 0;" ::: "memory");
        __syncthreads();
        if (g + 1 < NCHUNK) prefetch_chunk(((g + 1) & 1) ? B1 : B0, g + 1, tid);
        const char* Bc = (g & 1) ? B1 : B0;
#pragma unroll
        for (int ks = 0; ks < 2; ks++) {
            const int kl16 = kc * 2 + ks;
            const unsigned kcb = (unsigned)(kl16 >> 2) << 14;
            const unsigned cb0 = (unsigned)((kl16 & 3) * 32 + tp * 4);
            unsigned ah[2][4], al[2][4];
#pragma unroll
            for (int mt = 0; mt < 2; mt++)
#pragma unroll
                for (int rh = 0; rh < 2; rh++) {
                    unsigned a0 = kcb + arb[mt*2+rh] + (cb0 ^ am);
                    unsigned a1 = kcb + arb[mt*2+rh] + ((cb0 + 16u) ^ am);
                    ah[mt][rh]     = *(const unsigned*)(Ah + a0);
                    ah[mt][rh + 2] = *(const unsigned*)(Ah + a1);
                    al[mt][rh]     = *(const unsigned*)(Al + a0);
                    al[mt][rh + 2] = *(const unsigned*)(Al + a1);
                }
            const unsigned bk0 = (unsigned)(ks * 32 + tp * 4);
#pragma unroll
            for (int nt = 0; nt < 8; nt++) {
                const char* bb = Bc + brow + (unsigned)(nt * 1024);
                unsigned bh0 = *(const unsigned*)(bb + (bk0 ^ am));
                unsigned bh1 = *(const unsigned*)(bb + ((bk0 + 16u) ^ am));
                unsigned bl0 = *(const unsigned*)(bb + ((bk0 + 64u) ^ am));
                unsigned bl1 = *(const unsigned*)(bb + ((bk0 + 80u) ^ am));
#pragma unroll
                for (int mt = 0; mt < 2; mt++) {
                    mma_bf16(acc[mt][nt], ah[mt], bh0, bh1);
                    mma_bf16(acc[mt][nt], ah[mt], bl0, bl1);
                    mma_bf16(acc[mt][nt], al[mt], bh0, bh1);
                }
            }
        }
    }
    __syncthreads();
}

// LN epilogue on register fragments; optional logit partials (S1)
__device__ __forceinline__ void epi_ln_m(float acc[2][8][4],
    const float* bias, const float* gg, const float* bb,
    char* Ah, char* Al, float* ps, const float* us, float* lg,
    int wm, int wn4, int lane, bool do_logits)
{
    const int g8 = lane >> 2, tp = lane & 3;
    float s[4] = {0,0,0,0}, s2[4] = {0,0,0,0};
#pragma unroll
    for (int mt = 0; mt < 2; mt++)
#pragma unroll
        for (int nt = 0; nt < 8; nt++) {
            int C = wn4 * 64 + nt * 8 + tp * 2;
            float b0v = bias[C], b1v = bias[C + 1];
            float v0 = acc[mt][nt][0] + b0v, v1 = acc[mt][nt][1] + b1v;
            float v2 = acc[mt][nt][2] + b0v, v3 = acc[mt][nt][3] + b1v;
            acc[mt][nt][0]=v0; acc[mt][nt][1]=v1; acc[mt][nt][2]=v2; acc[mt][nt][3]=v3;
            s[mt*2]   += v0 + v1;  s2[mt*2]   += v0*v0 + v1*v1;
            s[mt*2+1] += v2 + v3;  s2[mt*2+1] += v2*v2 + v3*v3;
        }
#pragma unroll
    for (int off = 1; off <= 2; off <<= 1)
#pragma unroll
        for (int i = 0; i < 4; i++) {
            s[i]  += __shfl_xor_sync(0xffffffffu, s[i],  off);
            s2[i] += __shfl_xor_sync(0xffffffffu, s2[i], off);
        }
    if (tp == 0) {
#pragma unroll
        for (int i = 0; i < 4; i++) {
            int row = wm*32 + (i>>1)*16 + (i&1)*8 + g8;
            ps[(row*4 + wn4)*2]     = s[i];
            ps[(row*4 + wn4)*2 + 1] = s2[i];
        }
    }
    __syncthreads();
    float mean[4], rstd[4];
#pragma unroll
    for (int i = 0; i < 4; i++) {
        int row = wm*32 + (i>>1)*16 + (i&1)*8 + g8;
        float ss = 0.f, ss2 = 0.f;
#pragma unroll
        for (int x = 0; x < 4; x++) { ss += ps[(row*4+x)*2]; ss2 += ps[(row*4+x)*2+1]; }
        mean[i] = ss * (1.f/256.f);
        rstd[i] = rsqrtf(ss2 * (1.f/256.f) - mean[i]*mean[i] + LN_EPS);
    }
    float la[4][4];
    if (do_logits)
#pragma unroll
        for (int i = 0; i < 4; i++)
#pragma unroll
            for (int h = 0; h < 4; h++) la[i][h] = 0.f;
    const int half = wm >> 1;
#pragma unroll
    for (int mt = 0; mt < 2; mt++)
#pragma unroll
        for (int nt = 0; nt < 8; nt++) {
            int C = wn4 * 64 + nt * 8 + tp * 2;
            float g0 = gg[C], g1 = gg[C+1], e0 = bb[C], e1 = bb[C+1];
#pragma unroll
            for (int rh = 0; rh < 2; rh++) {
                int i = mt*2 + rh;
                int row = wm*32 + mt*16 + rh*8 + g8;
                float n0 = (acc[mt][nt][rh*2]   - mean[i]) * rstd[i] * g0 + e0;
                float n1 = (acc[mt][nt][rh*2+1] - mean[i]) * rstd[i] * g1 + e1;
                storeA2(Ah, Al, row, C, n0, n1);
                if (do_logits) {
                    float4 u0 = *(const float4*)(us + half*1024 + C*4);
                    float4 u1 = *(const float4*)(us + half*1024 + (C+1)*4);
                    la[i][0] += n0*u0.x + n1*u1.x;
                    la[i][1] += n0*u0.y + n1*u1.y;
                    la[i][2] += n0*u0.z + n1*u1.z;
                    la[i][3] += n0*u0.w + n1*u1.w;
                }
            }
        }
    if (do_logits) {
#pragma unroll
        for (int off = 1; off <= 2; off <<= 1)
#pragma unroll
            for (int i = 0; i < 4; i++)
#pragma unroll
                for (int h = 0; h < 4; h++)
                    la[i][h] += __shfl_xor_sync(0xffffffffu, la[i][h], off);
        if (tp == 0)
#pragma unroll
            for (int i = 0; i < 4; i++) {
                int row = wm*32 + (i>>1)*16 + (i&1)*8 + g8;
#pragma unroll
                for (int h = 0; h < 4; h++) lg[row*16 + wn4*4 + h] = la[i][h];
            }
    }
    __syncthreads();
}

__global__ void __launch_bounds__(512, 1) k2m(
    const float* __restrict__ x_stat,
    const float* __restrict__ b_stat, const float* __restrict__ g_nstat,
    const float* __restrict__ b_nstat, const float* __restrict__ bv,
    const float* __restrict__ g_mlp,  const float* __restrict__ b_mlp,
    const float* __restrict__ b1,     const float* __restrict__ b2,
    float* __restrict__ out)
{
    extern __shared__ char smc[];
    char*  Ah  = smc + O_AH;
    char*  Al  = smc + O_AL;
    char*  B0  = smc + O_B0;
    char*  B1  = smc + O_B1;
    float* pb  = (float*)(smc + O_PB);
    float* us  = (float*)(smc + O_US);
    float* ps  = (float*)(smc + O_PS);
    float* lg  = (float*)(smc + O_LG);
    float* zs  = (float*)(smc + O_LG);   // reuse after S1
    float* wns = (float*)(smc + O_WN);
    float* qbk = (float*)(smc + O_TAIL);
    float* ssm = (float*)(smc + O_TAIL + 32);

    const int tid = threadIdx.x, lane = tid & 31, w = tid >> 5;
    const int wm = w & 3, wn4 = w >> 2;
    const int g8 = lane >> 2, tp = lane & 3;
    const size_t b0 = (size_t)blockIdx.x * 2;

    // kick off chunk-0 copy immediately; it overlaps all staging below
    prefetch_chunk(B0, 0, tid);

    // ---- cooperative staging ----
    for (int idx = tid; idx < 2048; idx += 512) {
        int rr = idx >> 4, c4 = (idx & 15) * 4;
        float4 v = *reinterpret_cast<const float4*>(
            x_stat + (b0 + (rr >> 6)) * 4096 + (size_t)(rr & 63) * 64 + c4);
        storeA2(Ah, Al, rr, c4,     v.x, v.y);
        storeA2(Ah, Al, rr, c4 + 2, v.z, v.w);
    }
    if (tid < 512)
        reinterpret_cast<float4*>(us)[tid] =
            reinterpret_cast<const float4*>(g_u + b0 * 1024)[tid];
    if (tid < 64) {
        reinterpret_cast<float4*>(pb + 0*256)[tid] = reinterpret_cast<const float4*>(b_stat)[tid];
        reinterpret_cast<float4*>(pb + 1*256)[tid] = reinterpret_cast<const float4*>(g_nstat)[tid];
        reinterpret_cast<float4*>(pb + 2*256)[tid] = reinterpret_cast<const float4*>(b_nstat)[tid];
        reinterpret_cast<float4*>(pb + 3*256)[tid] = reinterpret_cast<const float4*>(bv)[tid];
        reinterpret_cast<float4*>(pb + 4*256)[tid] = reinterpret_cast<const float4*>(g_mlp)[tid];
        reinterpret_cast<float4*>(pb + 5*256)[tid] = reinterpret_cast<const float4*>(b_mlp)[tid];
        reinterpret_cast<float4*>(pb + 6*256)[tid] = reinterpret_cast<const float4*>(b1)[tid];
        reinterpret_cast<float4*>(pb + 7*256)[tid] = reinterpret_cast<const float4*>(b2)[tid];
    }
    if (tid < 8) qbk[tid] = g_qbk[b0 * 4 + tid];

    float acc[2][8][4];

    // ---- S1: s = x_stat @ W_stat ; LN -> A ; logit partials (chunks 0-1) ----
    gemm_tc(acc, Ah, Al, B0, B1, 0, 2, wm, wn4, lane, tid);
    epi_ln_m(acc, pb + 0*256, pb + 1*256, pb + 2*256, Ah, Al, ps, us, lg,
             wm, wn4, lane, true);

    // ---- logits -> sigmoid -> normalize -> w_mean ----
    {
        int row = tid >> 2, h = tid & 3;
        float lv = qbk[(row >> 6) * 4 + h];
#pragma unroll
        for (int x = 0; x < 4; x++) lv += lg[row*16 + x*4 + h];
        wns[tid] = 1.f / (1.f + expf(-lv * SCALE));
    }
    __syncthreads();
    if (tid < 8) {
        int half = tid >> 2, h = tid & 3;
        float sum = 0.f;
        for (int k = 0; k < 64; k++) sum += wns[(half*64 + k)*4 + h];
        ssm[tid] = sum + 1e-6f;
    }
    __syncthreads();
    wns[tid] = wns[tid] / ssm[(tid >> 8) * 4 + (tid & 3)];
    __syncthreads();
    if (tid < 128)
        out[(size_t)B_ROWS * DM + (b0 + (tid >> 6)) * 64 + (tid & 63)] =
            0.25f * (wns[tid*4] + wns[tid*4+1] + wns[tid*4+2] + wns[tid*4+3]);
    __syncthreads();

    // ---- S2: v = s @ Wv ; LN(g_mlp) -> A (chunks 2-9) ----
    gemm_tc(acc, Ah, Al, B0, B1, 2, 8, wm, wn4, lane, tid);
    epi_ln_m(acc, pb + 3*256, pb + 4*256, pb + 5*256, Ah, Al, ps, us, lg,
             wm, wn4, lane, false);

    // ---- S3: t = gelu(v @ W1 + b1) -> A (chunks 10-17) ----
    gemm_tc(acc, Ah, Al, B0, B1, 10, 8, wm, wn4, lane, tid);
#pragma unroll
    for (int mt = 0; mt < 2; mt++)
#pragma unroll
        for (int nt = 0; nt < 8; nt++) {
            int C = wn4 * 64 + nt * 8 + tp * 2;
            float e0 = pb[6*256 + C], e1 = pb[6*256 + C + 1];
#pragma unroll
            for (int rh = 0; rh < 2; rh++) {
                int row = wm*32 + mt*16 + rh*8 + g8;
                float x0 = acc[mt][nt][rh*2]   + e0;
                float x1 = acc[mt][nt][rh*2+1] + e1;
                float n0 = 0.5f * x0 * (1.f + erff(x0 * 0.70710678118f));
                float n1 = 0.5f * x1 * (1.f + erff(x1 * 0.70710678118f));
                storeA2(Ah, Al, row, C, n0, n1);
            }
        }
    __syncthreads();

    // ---- S4: vtok = t @ W2 + b2 ; weighted column sums -> z (chunks 18-25) ----
    gemm_tc(acc, Ah, Al, B0, B1, 18, 8, wm, wn4, lane, tid);
    if (tid < 512) zs[tid] = 0.f;
    __syncthreads();
    {
        float z0[8], z1[8];
#pragma unroll
        for (int nt = 0; nt < 8; nt++) { z0[nt] = 0.f; z1[nt] = 0.f; }
#pragma unroll
        for (int mt = 0; mt < 2; mt++)
#pragma unroll
            for (int nt = 0; nt < 8; nt++) {
                int C = wn4 * 64 + nt * 8 + tp * 2;
                int hcol = C >> 6;
                float e0 = pb[7*256 + C], e1 = pb[7*256 + C + 1];
#pragma unroll
                for (int rh = 0; rh < 2; rh++) {
                    int row = wm*32 + mt*16 + rh*8 + g8;
                    float wf = wns[row*4 + hcol];
                    z0[nt] += (acc[mt][nt][rh*2]   + e0) * wf;
                    z1[nt] += (acc[mt][nt][rh*2+1] + e1) * wf;
                }
            }
#pragma unroll
        for (int off = 4; off <= 16; off <<= 1)
#pragma unroll
            for (int nt = 0; nt < 8; nt++) {
                z0[nt] += __shfl_xor_sync(0xffffffffu, z0[nt], off);
                z1[nt] += __shfl_xor_sync(0xffffffffu, z1[nt], off);
            }
        if (lane < 4) {
            int half = wm >> 1;
#pragma unroll
            for (int nt = 0; nt < 8; nt++) {
                int C = wn4 * 64 + nt * 8 + lane * 2;
                atomicAdd(&zs[half*256 + C],     z0[nt]);
                atomicAdd(&zs[half*256 + C + 1], z1[nt]);
            }
        }
    }
    __syncthreads();
    g_z[b0 * 256 + tid] = zs[tid];
}

// ---------------- k3: c = z @ Wo + bo ; out = h0 + rs*c ----------------
__global__ void __launch_bounds__(256, 1) k3(
    const float* __restrict__ Wo, const float* __restrict__ bo,
    const float* __restrict__ res_p, float* __restrict__ out)
{
    extern __shared__ float sm[];
    float* zsm = sm;                       // 32*256
    float* Wt  = zsm + 32 * 256;           // 16*260
    float* pbo = Wt + 16 * WT_STRIDE;      // 256
    const int tid = threadIdx.x, row0 = blockIdx.x * 32;
    for (int f = tid; f < 2048; f += 256)
        reinterpret_cast<float4*>(zsm)[f] =
            reinterpret_cast<const float4*>(g_z + (size_t)row0 * 256)[f];
    if (tid < 64)
        reinterpret_cast<float4*>(pbo)[tid] = reinterpret_cast<const float4*>(bo)[tid];
    __syncthreads();
    float acc[4][8];
    gemm_acc<256>(zsm, 256, 256, Wo, Wt, acc, tid);
    const float rs = *res_p;
    const int tc = tid & 31, tok0 = (tid >> 5) * 4, col0 = tc * 8;
#pragma unroll
    for (int t = 0; t < 4; t++) {
        const size_t r = (size_t)(row0 + tok0 + t);
#pragma unroll
        for (int j = 0; j < 8; j++)
            out[r * 256 + col0 + j] =
                g_h0[r * 256 + col0 + j] + rs * (acc[t][j] + pbo[col0 + j]);
    }
}

// ============================================================
extern "C" void kernel_launch(void* const* d_in, const int* in_sizes, int n_in,
                              void* d_out, int out_size)
{
    const float* h_dyn   = (const float*)d_in[0];
    const float* x_stat  = (const float*)d_in[1];
    const float* W_dyn   = (const float*)d_in[2];
    const float* b_dyn   = (const float*)d_in[3];
    const float* W_stat  = (const float*)d_in[4];
    const float* b_stat  = (const float*)d_in[5];
    const float* g_ndyn  = (const float*)d_in[6];
    const float* b_ndyn  = (const float*)d_in[7];
    const float* g_nstat = (const float*)d_in[8];
    const float* b_nstat = (const float*)d_in[9];
    const float* Wq  = (const float*)d_in[10];
    const float* bq  = (const float*)d_in[11];
    const float* Wk  = (const float*)d_in[12];
    const float* bk  = (const float*)d_in[13];
    const float* Wv  = (const float*)d_in[14];
    const float* bv  = (const float*)d_in[15];
    const float* g_mlp = (const float*)d_in[16];
    const float* b_mlp = (const float*)d_in[17];
    const float* W1  = (const float*)d_in[18];
    const float* b1  = (const float*)d_in[19];
    const float* W2  = (const float*)d_in[20];
    const float* b2  = (const float*)d_in[21];
    const float* Wo  = (const float*)d_in[22];
    const float* bo  = (const float*)d_in[23];
    const float* res_sc = (const float*)d_in[24];
    float* out = (float*)d_out;

    const int SMEM1 = (32*512 + 32*256 + 32*256 + 16*WT_STRIDE + 5*256) * 4;
    const int SMEM3 = (32*256 + 16*WT_STRIDE + 256) * 4;
    cudaFuncSetAttribute(k1,  cudaFuncAttributeMaxDynamicSharedMemorySize, SMEM1);
    cudaFuncSetAttribute(k2m, cudaFuncAttributeMaxDynamicSharedMemorySize, SMEM2);
    cudaFuncSetAttribute(k3,  cudaFuncAttributeMaxDynamicSharedMemorySize, SMEM3);

    k0<<<NCHUNK, 256>>>(W_stat, Wv, W1, W2);
    k1<<<B_ROWS / 32, 256, SMEM1>>>(h_dyn, W_dyn, b_dyn, g_ndyn, b_ndyn, Wq, bq, Wk, bk);
    k2m<<<B_ROWS / 2, 512, SMEM2>>>(x_stat, b_stat, g_nstat, b_nstat, bv,
                                    g_mlp, b_mlp, b1, b2, out);
    k3<<<B_ROWS / 32, 256, SMEM3>>>(Wo, bo, res_sc, out);
}